// round 10
// baseline (speedup 1.0000x reference)
#include <cuda_runtime.h>
#include <cuda_bf16.h>
#include <math.h>
#include <stdint.h>

#define T_TOK 4096
#define D_MODEL 2048
#define S_SEQ 2048
#define NH 16
#define NKV 4
#define HDIM 128
#define NE 8
#define NF 1024
#define LIST_STRIDE (2 * T_TOK)

// ---------------- scratch (static device allocations; no cudaMalloc) ----------------
__device__ float g_q  [T_TOK * NH * HDIM];
__device__ float g_k  [T_TOK * NKV * HDIM];
__device__ float g_x2 [T_TOK * D_MODEL];
__device__ float g_h2 [T_TOK * D_MODEL];
__device__ int   g_toklist[NE * LIST_STRIDE];
__device__ float g_entrygate[2 * T_TOK];
__device__ int   g_expcnt[NE];

// bf16 hi/lo split buffers
__device__ __nv_bfloat16 g_h_hi [T_TOK * D_MODEL],  g_h_lo [T_TOK * D_MODEL];
__device__ __nv_bfloat16 g_h2_hi[T_TOK * D_MODEL],  g_h2_lo[T_TOK * D_MODEL];
__device__ __nv_bfloat16 g_o_hi [T_TOK * D_MODEL],  g_o_lo [T_TOK * D_MODEL];
__device__ __nv_bfloat16 g_k_hi [T_TOK * NKV * HDIM], g_k_lo [T_TOK * NKV * HDIM];
__device__ __nv_bfloat16 g_v_hi [T_TOK * NKV * HDIM], g_v_lo [T_TOK * NKV * HDIM];
__device__ __nv_bfloat16 g_act_hi[T_TOK * 2 * NF],  g_act_lo[T_TOK * 2 * NF];
// packed QKV weights: rows 0..2047 wq, 2048..2559 wk, 2560..3071 wv
__device__ __nv_bfloat16 g_wqkv_hi[3072 * 2048], g_wqkv_lo[3072 * 2048];
__device__ __nv_bfloat16 g_wo_hi[2048 * 2048], g_wo_lo[2048 * 2048];
// interleaved gate/up: per expert 2048 rows, row 2f = wg[f], 2f+1 = wu[f]
__device__ __nv_bfloat16 g_wgu_hi[NE * 2048 * D_MODEL], g_wgu_lo[NE * 2048 * D_MODEL];
__device__ __nv_bfloat16 g_wd_hi[NE * D_MODEL * NF], g_wd_lo[NE * D_MODEL * NF];

// ---------------- PTX helpers ----------------
__device__ __forceinline__ uint32_t smem_u32(const void* p) {
    return (uint32_t)__cvta_generic_to_shared(p);
}
__device__ __forceinline__ void cpa16(uint32_t dst, const void* src) {
    asm volatile("cp.async.cg.shared.global [%0], [%1], 16;" :: "r"(dst), "l"(src));
}
__device__ __forceinline__ void cp_commit() { asm volatile("cp.async.commit_group;" ::: "memory"); }
__device__ __forceinline__ void cp_wait1()  { asm volatile("cp.async.wait_group 1;" ::: "memory"); }
__device__ __forceinline__ void cp_wait0()  { asm volatile("cp.async.wait_group 0;" ::: "memory"); }

__device__ __forceinline__ void ldsm_x4(uint32_t r[4], uint32_t addr) {
    asm volatile("ldmatrix.sync.aligned.m8n8.x4.shared.b16 {%0,%1,%2,%3}, [%4];"
                 : "=r"(r[0]), "=r"(r[1]), "=r"(r[2]), "=r"(r[3]) : "r"(addr));
}
__device__ __forceinline__ void ldsm_x4_t(uint32_t r[4], uint32_t addr) {
    asm volatile("ldmatrix.sync.aligned.m8n8.x4.trans.shared.b16 {%0,%1,%2,%3}, [%4];"
                 : "=r"(r[0]), "=r"(r[1]), "=r"(r[2]), "=r"(r[3]) : "r"(addr));
}
__device__ __forceinline__ void mma_16816(float acc[4], const uint32_t a[4], const uint32_t b[2]) {
    asm volatile(
        "mma.sync.aligned.m16n8k16.row.col.f32.bf16.bf16.f32 "
        "{%0,%1,%2,%3}, {%4,%5,%6,%7}, {%8,%9}, {%0,%1,%2,%3};"
        : "+f"(acc[0]), "+f"(acc[1]), "+f"(acc[2]), "+f"(acc[3])
        : "r"(a[0]), "r"(a[1]), "r"(a[2]), "r"(a[3]), "r"(b[0]), "r"(b[1]));
}
__device__ __forceinline__ void split_store(float v, __nv_bfloat16* hp, __nv_bfloat16* lp) {
    __nv_bfloat16 h = __float2bfloat16_rn(v);
    *hp = h;
    *lp = __float2bfloat16_rn(v - __bfloat162float(h));
}
__device__ __forceinline__ uint32_t bf2u(__nv_bfloat162 h) {
    uint32_t u;
    asm("mov.b32 %0, {%1, %2};" : "=r"(u)
        : "h"(__bfloat16_as_ushort(h.x)), "h"(__bfloat16_as_ushort(h.y)));
    return u;
}

// ---------------- fp32 -> bf16 hi/lo split (contiguous) ----------------
__global__ void split_kernel(const float4* __restrict__ s, __nv_bfloat162* __restrict__ hi,
                             __nv_bfloat162* __restrict__ lo, int n4) {
    int i = blockIdx.x * blockDim.x + threadIdx.x;
    int stride = gridDim.x * blockDim.x;
    for (; i < n4; i += stride) {
        float4 v = s[i];
        __nv_bfloat162 h0 = __floats2bfloat162_rn(v.x, v.y);
        __nv_bfloat162 h1 = __floats2bfloat162_rn(v.z, v.w);
        hi[i * 2 + 0] = h0;
        hi[i * 2 + 1] = h1;
        lo[i * 2 + 0] = __floats2bfloat162_rn(v.x - __bfloat162float(h0.x),
                                              v.y - __bfloat162float(h0.y));
        lo[i * 2 + 1] = __floats2bfloat162_rn(v.z - __bfloat162float(h1.x),
                                              v.w - __bfloat162float(h1.y));
    }
}

// ---------------- gate/up interleaving split: src (e,f,d) -> dst row e*2048 + 2f + sel ----
__global__ void split_interleave(const float4* __restrict__ s, __nv_bfloat162* __restrict__ hi,
                                 __nv_bfloat162* __restrict__ lo, int sel) {
    int n4 = NE * NF * (D_MODEL / 4);
    int i = blockIdx.x * blockDim.x + threadIdx.x;
    int stride = gridDim.x * blockDim.x;
    for (; i < n4; i += stride) {
        float4 v = s[i];
        int d4 = i & 511;              // (d/4)
        int fidx = i >> 9;             // e*NF + f
        int f = fidx & (NF - 1);
        int e = fidx >> 10;
        size_t dst2 = ((size_t)(e * 2048 + 2 * f + sel) * 512 + d4) * 2;
        __nv_bfloat162 h0 = __floats2bfloat162_rn(v.x, v.y);
        __nv_bfloat162 h1 = __floats2bfloat162_rn(v.z, v.w);
        hi[dst2 + 0] = h0;
        hi[dst2 + 1] = h1;
        lo[dst2 + 0] = __floats2bfloat162_rn(v.x - __bfloat162float(h0.x),
                                             v.y - __bfloat162float(h0.y));
        lo[dst2 + 1] = __floats2bfloat162_rn(v.z - __bfloat162float(h1.x),
                                             v.w - __bfloat162float(h1.y));
    }
}

// ---------------- rmsnorm + split ----------------
__global__ void rmsnorm_split(const float* __restrict__ x, const float* __restrict__ w,
                              float* __restrict__ outf, __nv_bfloat16* __restrict__ hi,
                              __nv_bfloat16* __restrict__ lo) {
    int row = blockIdx.x;
    int tid = threadIdx.x;  // 256
    const float* xr = x + (size_t)row * D_MODEL;
    float xv[8];
    float ss = 0.f;
#pragma unroll
    for (int i = 0; i < 8; i++) {
        xv[i] = xr[tid + i * 256];
        ss += xv[i] * xv[i];
    }
#pragma unroll
    for (int o = 16; o > 0; o >>= 1) ss += __shfl_xor_sync(0xffffffffu, ss, o);
    __shared__ float sred[8];
    if ((tid & 31) == 0) sred[tid >> 5] = ss;
    __syncthreads();
    float tot = 0.f;
#pragma unroll
    for (int i = 0; i < 8; i++) tot += sred[i];
    float rs = rsqrtf(tot / (float)D_MODEL + 1e-6f);
    size_t base = (size_t)row * D_MODEL;
#pragma unroll
    for (int i = 0; i < 8; i++) {
        int d = tid + i * 256;
        float v = xv[i] * rs * w[d];
        if (outf) outf[base + d] = v;
        split_store(v, hi + base + d, lo + base + d);
    }
}

// ---------------- per-head rmsnorm + RoPE: one WARP per head ----------------
__global__ void qknorm_rope(float* __restrict__ data, const float* __restrict__ w, int nheads,
                            __nv_bfloat16* __restrict__ hi, __nv_bfloat16* __restrict__ lo) {
    int gw = blockIdx.x * 8 + (threadIdx.x >> 5);
    int lane = threadIdx.x & 31;
    int t = gw / nheads;
    int h = gw - t * nheads;
    size_t off = ((size_t)t * nheads + h) * HDIM + lane * 4;
    float4 v = *(float4*)&data[off];
    float ss = v.x * v.x + v.y * v.y + v.z * v.z + v.w * v.w;
#pragma unroll
    for (int o = 16; o > 0; o >>= 1) ss += __shfl_xor_sync(0xffffffffu, ss, o);
    float rs = rsqrtf(ss * (1.f / 128.f) + 1e-6f);
    const float4 wv = *(const float4*)&w[lane * 4];
    v.x *= rs * wv.x; v.y *= rs * wv.y; v.z *= rs * wv.z; v.w *= rs * wv.w;
    float4 p;
    p.x = __shfl_xor_sync(0xffffffffu, v.x, 16);
    p.y = __shfl_xor_sync(0xffffffffu, v.y, 16);
    p.z = __shfl_xor_sync(0xffffffffu, v.z, 16);
    p.w = __shfl_xor_sync(0xffffffffu, v.w, 16);
    int s = t & (S_SEQ - 1);
    int ibase = (lane * 4) & 63;
    bool lohalf = lane < 16;
    float o4[4];
    float vv[4] = {v.x, v.y, v.z, v.w};
    float pp[4] = {p.x, p.y, p.z, p.w};
#pragma unroll
    for (int c = 0; c < 4; c++) {
        float fi = exp2f(-(float)(ibase + c) * 0.20762050592154265f);
        float ang = (float)s * fi;
        float sn, cs;
        sincosf(ang, &sn, &cs);
        o4[c] = lohalf ? (vv[c] * cs - pp[c] * sn) : (pp[c] * sn + vv[c] * cs);
    }
    if (hi) {
#pragma unroll
        for (int c = 0; c < 4; c++) split_store(o4[c], hi + off + c, lo + off + c);
    } else {
        *(float4*)&data[off] = make_float4(o4[0], o4[1], o4[2], o4[3]);
    }
}

// ---------------- HMMA causal flash attention ----------------
#define AT_SMEM (65536 + 2 * 65536)

__device__ __forceinline__ uint32_t tile_addr(uint32_t base, int row, int chunk) {
    return base + (uint32_t)(row * 256) + (uint32_t)((chunk ^ (row & 7)) << 4);
}

__global__ __launch_bounds__(256, 1) void attn_hmma(
    const float* __restrict__ Q,
    const __nv_bfloat16* __restrict__ Kh, const __nv_bfloat16* __restrict__ Kl,
    const __nv_bfloat16* __restrict__ Vh, const __nv_bfloat16* __restrict__ Vl,
    __nv_bfloat16* __restrict__ Ohi, __nv_bfloat16* __restrict__ Olo) {
    extern __shared__ char dsm[];
    uint32_t sb = smem_u32(dsm);
    const uint32_t Qh_s = sb, Ql_s = sb + 32768u;
    int qb = 15 - (int)blockIdx.x;
    int h = blockIdx.y, b = blockIdx.z;
    int tid = threadIdx.x;
    int w = tid >> 5, lane = tid & 31;
    int kvh = h >> 2;
    int qg = lane >> 3, sub = lane & 7;
    int qr = lane >> 2, qc2 = (lane & 3) * 2;
    const float e2 = 0.12751743f;  // log2(e)/sqrt(128)

#pragma unroll
    for (int i = 0; i < 16; i++) {
        int idx = i * 256 + tid;
        int row = idx >> 5;
        int d4 = (idx & 31) * 4;
        const float4 v = *(const float4*)&Q[(((size_t)(b * S_SEQ + qb * 128 + row) * NH + h) << 7) + d4];
        __nv_bfloat162 h0 = __floats2bfloat162_rn(v.x, v.y);
        __nv_bfloat162 h1 = __floats2bfloat162_rn(v.z, v.w);
        __nv_bfloat162 l0v = __floats2bfloat162_rn(v.x - __bfloat162float(h0.x),
                                                   v.y - __bfloat162float(h0.y));
        __nv_bfloat162 l1v = __floats2bfloat162_rn(v.z - __bfloat162float(h1.x),
                                                   v.w - __bfloat162float(h1.y));
        uint32_t a = (uint32_t)(row * 256 + (((d4 >> 3) ^ (row & 7)) << 4) + (d4 & 7) * 2);
        *(__nv_bfloat162*)(dsm + a) = h0;
        *(__nv_bfloat162*)(dsm + a + 4) = h1;
        *(__nv_bfloat162*)(dsm + 32768 + a) = l0v;
        *(__nv_bfloat162*)(dsm + 32768 + a + 4) = l1v;
    }

    auto prefetch = [&](int kb, int buf) {
        uint32_t base = sb + 65536u + (uint32_t)buf * 65536u;
#pragma unroll
        for (int i = 0; i < 16; i++) {
            int ci = i * 256 + tid;
            int mat = ci >> 10;
            int idx = ci & 1023;
            int row = idx >> 4, chunk = idx & 15;
            uint32_t dst = tile_addr(base + (uint32_t)mat * 16384u, row, chunk);
            size_t goff = (((size_t)(b * S_SEQ + kb * 64 + row) * NKV + kvh) << 7) + chunk * 8;
            const __nv_bfloat16* src;
            if (mat == 0) src = Kh + goff;
            else if (mat == 1) src = Kl + goff;
            else if (mat == 2) src = Vh + goff;
            else src = Vl + goff;
            cpa16(dst, src);
        }
        cp_commit();
    };

    float Oa[16][4];
#pragma unroll
    for (int d = 0; d < 16; d++)
#pragma unroll
        for (int j = 0; j < 4; j++) Oa[d][j] = 0.f;
    float m0 = -1e30f, m1 = -1e30f, l0 = 0.f, l1 = 0.f;

    int nkb = 2 * qb + 2;
    prefetch(0, 0);

    for (int kb = 0; kb < nkb; kb++) {
        cp_wait0();
        __syncthreads();
        if (kb + 1 < nkb) prefetch(kb + 1, (kb + 1) & 1);
        uint32_t kv = sb + 65536u + (uint32_t)(kb & 1) * 65536u;
        uint32_t Kh_t = kv, Kl_t = kv + 16384u, Vh_t = kv + 32768u, Vl_t = kv + 49152u;

        float s[8][4];
#pragma unroll
        for (int nb = 0; nb < 8; nb++)
#pragma unroll
            for (int j = 0; j < 4; j++) s[nb][j] = 0.f;

#pragma unroll
        for (int kc = 0; kc < 8; kc++) {
            uint32_t ah[4], al[4];
            int arow = w * 16 + (qg & 1) * 8 + sub;
            int achk = kc * 2 + (qg >> 1);
            ldsm_x4(ah, tile_addr(Qh_s, arow, achk));
            ldsm_x4(al, tile_addr(Ql_s, arow, achk));
#pragma unroll
            for (int nbp = 0; nbp < 4; nbp++) {
                uint32_t bh[4], bl[4];
                int brow = nbp * 16 + (qg >> 1) * 8 + sub;
                int bchk = kc * 2 + (qg & 1);
                ldsm_x4(bh, tile_addr(Kh_t, brow, bchk));
                ldsm_x4(bl, tile_addr(Kl_t, brow, bchk));
                mma_16816(s[2 * nbp + 0], ah, bh + 0);
                mma_16816(s[2 * nbp + 0], ah, bl + 0);
                mma_16816(s[2 * nbp + 0], al, bh + 0);
                mma_16816(s[2 * nbp + 1], ah, bh + 2);
                mma_16816(s[2 * nbp + 1], ah, bl + 2);
                mma_16816(s[2 * nbp + 1], al, bh + 2);
            }
        }

        int row0 = qb * 128 + w * 16 + qr;
        int row1 = row0 + 8;
        if (kb >= 2 * qb) {
            int colb = kb * 64 + qc2;
#pragma unroll
            for (int nb = 0; nb < 8; nb++) {
                int c0 = colb + nb * 8, c1 = c0 + 1;
                if (c0 > row0) s[nb][0] = -1e30f;
                if (c1 > row0) s[nb][1] = -1e30f;
                if (c0 > row1) s[nb][2] = -1e30f;
                if (c1 > row1) s[nb][3] = -1e30f;
            }
        }
        float mx0 = -1e30f, mx1 = -1e30f;
#pragma unroll
        for (int nb = 0; nb < 8; nb++) {
            mx0 = fmaxf(mx0, fmaxf(s[nb][0], s[nb][1]));
            mx1 = fmaxf(mx1, fmaxf(s[nb][2], s[nb][3]));
        }
        mx0 = fmaxf(mx0, __shfl_xor_sync(0xffffffffu, mx0, 1));
        mx0 = fmaxf(mx0, __shfl_xor_sync(0xffffffffu, mx0, 2));
        mx1 = fmaxf(mx1, __shfl_xor_sync(0xffffffffu, mx1, 1));
        mx1 = fmaxf(mx1, __shfl_xor_sync(0xffffffffu, mx1, 2));
        float mn0 = fmaxf(m0, mx0), mn1 = fmaxf(m1, mx1);
        float f0 = exp2f((m0 - mn0) * e2), f1 = exp2f((m1 - mn1) * e2);
        m0 = mn0; m1 = mn1;
        l0 *= f0; l1 *= f1;
#pragma unroll
        for (int d = 0; d < 16; d++) {
            Oa[d][0] *= f0; Oa[d][1] *= f0;
            Oa[d][2] *= f1; Oa[d][3] *= f1;
        }
#pragma unroll
        for (int nb = 0; nb < 8; nb++) {
            s[nb][0] = exp2f((s[nb][0] - mn0) * e2);
            s[nb][1] = exp2f((s[nb][1] - mn0) * e2);
            s[nb][2] = exp2f((s[nb][2] - mn1) * e2);
            s[nb][3] = exp2f((s[nb][3] - mn1) * e2);
            l0 += s[nb][0] + s[nb][1];
            l1 += s[nb][2] + s[nb][3];
        }

#pragma unroll
        for (int kk = 0; kk < 4; kk++) {
            uint32_t ph[4], pl[4];
            float* p0 = s[2 * kk];
            float* p1 = s[2 * kk + 1];
            __nv_bfloat162 h00 = __floats2bfloat162_rn(p0[0], p0[1]);
            __nv_bfloat162 h01 = __floats2bfloat162_rn(p0[2], p0[3]);
            __nv_bfloat162 h10 = __floats2bfloat162_rn(p1[0], p1[1]);
            __nv_bfloat162 h11 = __floats2bfloat162_rn(p1[2], p1[3]);
            ph[0] = bf2u(h00); ph[1] = bf2u(h01);
            ph[2] = bf2u(h10); ph[3] = bf2u(h11);
            pl[0] = bf2u(__floats2bfloat162_rn(p0[0] - __bfloat162float(h00.x),
                                               p0[1] - __bfloat162float(h00.y)));
            pl[1] = bf2u(__floats2bfloat162_rn(p0[2] - __bfloat162float(h01.x),
                                               p0[3] - __bfloat162float(h01.y)));
            pl[2] = bf2u(__floats2bfloat162_rn(p1[0] - __bfloat162float(h10.x),
                                               p1[1] - __bfloat162float(h10.y)));
            pl[3] = bf2u(__floats2bfloat162_rn(p1[2] - __bfloat162float(h11.x),
                                               p1[3] - __bfloat162float(h11.y)));
#pragma unroll
            for (int dbp = 0; dbp < 8; dbp++) {
                uint32_t vh[4], vl[4];
                int vrow = kk * 16 + (qg & 1) * 8 + sub;
                int vchk = dbp * 2 + (qg >> 1);
                ldsm_x4_t(vh, tile_addr(Vh_t, vrow, vchk));
                ldsm_x4_t(vl, tile_addr(Vl_t, vrow, vchk));
                mma_16816(Oa[2 * dbp + 0], ph, vh + 0);
                mma_16816(Oa[2 * dbp + 0], ph, vl + 0);
                mma_16816(Oa[2 * dbp + 0], pl, vh + 0);
                mma_16816(Oa[2 * dbp + 1], ph, vh + 2);
                mma_16816(Oa[2 * dbp + 1], ph, vl + 2);
                mma_16816(Oa[2 * dbp + 1], pl, vh + 2);
            }
        }
    }

    l0 += __shfl_xor_sync(0xffffffffu, l0, 1);
    l0 += __shfl_xor_sync(0xffffffffu, l0, 2);
    l1 += __shfl_xor_sync(0xffffffffu, l1, 1);
    l1 += __shfl_xor_sync(0xffffffffu, l1, 2);
    float i0 = 1.f / l0, i1 = 1.f / l1;
    int row0 = qb * 128 + w * 16 + qr;
#pragma unroll
    for (int db = 0; db < 16; db++) {
        int col = h * 128 + db * 8 + qc2;
        size_t a0 = ((size_t)(b * S_SEQ + row0) << 11) + col;
        size_t a1 = ((size_t)(b * S_SEQ + row0 + 8) << 11) + col;
        float v0 = Oa[db][0] * i0, v1 = Oa[db][1] * i0;
        float v2 = Oa[db][2] * i1, v3 = Oa[db][3] * i1;
        __nv_bfloat162 h0 = __floats2bfloat162_rn(v0, v1);
        __nv_bfloat162 h1 = __floats2bfloat162_rn(v2, v3);
        *(__nv_bfloat162*)&Ohi[a0] = h0;
        *(__nv_bfloat162*)&Ohi[a1] = h1;
        *(__nv_bfloat162*)&Olo[a0] = __floats2bfloat162_rn(v0 - __bfloat162float(h0.x),
                                                           v1 - __bfloat162float(h0.y));
        *(__nv_bfloat162*)&Olo[a1] = __floats2bfloat162_rn(v2 - __bfloat162float(h1.x),
                                                           v3 - __bfloat162float(h1.y));
    }
}

// ---------------- router ----------------
__global__ void zero_cnt_kernel() { g_expcnt[threadIdx.x] = 0; }

__global__ void router_kernel(const float* __restrict__ h2, const float* __restrict__ wr) {
    int t = blockIdx.x;
    int tid = threadIdx.x;  // 256
    float p[8];
#pragma unroll
    for (int e = 0; e < 8; e++) p[e] = 0.f;
#pragma unroll
    for (int i = 0; i < 8; i++) {
        int d = tid + i * 256;
        float hv = h2[(size_t)t * D_MODEL + d];
#pragma unroll
        for (int e = 0; e < 8; e++) p[e] += hv * wr[e * D_MODEL + d];
    }
    __shared__ float red[8][256];
#pragma unroll
    for (int e = 0; e < 8; e++) red[e][tid] = p[e];
    __syncthreads();
    for (int stp = 128; stp > 0; stp >>= 1) {
        if (tid < stp) {
#pragma unroll
            for (int e = 0; e < 8; e++) red[e][tid] += red[e][tid + stp];
        }
        __syncthreads();
    }
    if (tid == 0) {
        float lg[8];
        float m = -1e30f;
#pragma unroll
        for (int e = 0; e < 8; e++) { lg[e] = red[e][0]; m = fmaxf(m, lg[e]); }
        float pr[8];
#pragma unroll
        for (int e = 0; e < 8; e++) pr[e] = __expf(lg[e] - m);
        int i1 = 0;
#pragma unroll
        for (int e = 1; e < 8; e++) if (pr[e] > pr[i1]) i1 = e;
        int i2 = (i1 == 0) ? 1 : 0;
#pragma unroll
        for (int e = 0; e < 8; e++) if (e != i1 && pr[e] > pr[i2]) i2 = e;
        float v1 = pr[i1], v2 = pr[i2];
        float denom = v1 + v2;
        int pos1 = atomicAdd(&g_expcnt[i1], 1);
        g_toklist[i1 * LIST_STRIDE + pos1] = t * 2;
        g_entrygate[t * 2] = v1 / denom;
        int pos2 = atomicAdd(&g_expcnt[i2], 1);
        g_toklist[i2 * LIST_STRIDE + pos2] = t * 2 + 1;
        g_entrygate[t * 2 + 1] = v2 / denom;
    }
}

// ---------------- HMMA bf16x3 GEMM: C[M,N] = A @ B^T ----------------
// CTA tile M=256, N=128, BK=32. 8 warps in 4x2 grid, warp tile 64x64.
// modes: 0 dense fp32 (+resid/aux dup), 2 MoE-down atomic, 4 MoE gate/up interleaved
// + silu -> act split, 6 fused QKV epilogue (Q fp32 / K fp32 / V split).
#define STAGE_BYTES 49152
#define HM_SMEM (3 * STAGE_BYTES)

__device__ __forceinline__ uint32_t sw_addr(uint32_t base, int row, int kchunk) {
    return base + (uint32_t)(row * 64) + (uint32_t)((kchunk ^ ((row >> 1) & 3)) << 4);
}

__global__ __launch_bounds__(256, 1) void hmma_gemm(
    const __nv_bfloat16* __restrict__ Ahi, const __nv_bfloat16* __restrict__ Alo,
    const __nv_bfloat16* __restrict__ Bhi, const __nv_bfloat16* __restrict__ Blo,
    float* __restrict__ C, int N, int K,
    const float* __restrict__ resid, float* __restrict__ aux, int mode) {
    extern __shared__ char dsm[];
    __shared__ int arowS[256];
    __shared__ int crowS[256];

    int tid = threadIdx.x;
    int n0 = blockIdx.x * 128;
    int mb = blockIdx.y * 256;
    int e = blockIdx.z;
    int cnt = 1 << 30;
    bool moe = (mode == 2 || mode == 4);
    if (moe) {
        cnt = g_expcnt[e];
        if (mb >= cnt) return;
        size_t boff = (size_t)e * N * K;
        Bhi += boff;
        Blo += boff;
    }
    if (moe) {
        int idx = mb + tid;
        if (idx > cnt - 1) idx = cnt - 1;
        int entry = g_toklist[e * LIST_STRIDE + idx];
        crowS[tid] = entry;
        arowS[tid] = (mode == 4) ? (entry >> 1) : entry;
    } else {
        arowS[tid] = mb + tid;
        crowS[tid] = mb + tid;
    }
    __syncthreads();

    uint32_t sb = smem_u32(dsm);

    // stage layout: Ahi 16K | Alo 16K | Bhi 8K | Blo 8K
    auto load_tile = [&](int stage, int k0) {
        uint32_t sbase = sb + (uint32_t)stage * STAGE_BYTES;
#pragma unroll
        for (int i = 0; i < 12; i++) {
            int ci = i * 256 + tid;  // 0..3071
            if (ci < 2048) {
                int matl = ci >> 10;         // 0=Ahi 1=Alo
                int idx = ci & 1023;
                int r = idx >> 2, c = idx & 3;
                uint32_t dst = sw_addr(sbase + (uint32_t)matl * 16384u, r, c);
                const __nv_bfloat16* src = (matl ? Alo : Ahi) + (size_t)arowS[r] * K + k0 + c * 8;
                cpa16(dst, src);
            } else {
                int cj = ci - 2048;
                int matl = cj >> 9;          // 0=Bhi 1=Blo
                int idx = cj & 511;
                int r = idx >> 2, c = idx & 3;
                uint32_t dst = sw_addr(sbase + 32768u + (uint32_t)matl * 8192u, r, c);
                const __nv_bfloat16* src = (matl ? Blo : Bhi) + (size_t)(n0 + r) * K + k0 + c * 8;
                cpa16(dst, src);
            }
        }
        cp_commit();
    };

    int T = K >> 5;
    load_tile(0, 0);
    load_tile(1, 32);

    int warp = tid >> 5, lane = tid & 31;
    int wm = warp >> 1, wn = warp & 1;  // warp tile 64x64
    int q = lane >> 3, sub = lane & 7;

    float acc[4][8][4];
#pragma unroll
    for (int mi = 0; mi < 4; mi++)
#pragma unroll
        for (int nj = 0; nj < 8; nj++)
#pragma unroll
            for (int v = 0; v < 4; v++) acc[mi][nj][v] = 0.f;

    for (int kt = 0; kt < T; kt++) {
        if (kt < T - 1) cp_wait1(); else cp_wait0();
        __syncthreads();
        if (kt + 2 < T) load_tile((kt + 2) % 3, (kt + 2) * 32);
        uint32_t sbase = sb + (uint32_t)(kt % 3) * STAGE_BYTES;
        uint32_t aH = sbase, aL = sbase + 16384u, bH = sbase + 32768u, bL = sbase + 40960u;
#pragma unroll
        for (int ks = 0; ks < 2; ks++) {
            uint32_t ah[4][4], al[4][4], bh[4][4], bl[4][4];
#pragma unroll
            for (int mi = 0; mi < 4; mi++) {
                int row = wm * 64 + mi * 16 + (q & 1) * 8 + sub;
                int kc = ks * 2 + (q >> 1);
                ldsm_x4(ah[mi], sw_addr(aH, row, kc));
                ldsm_x4(al[mi], sw_addr(aL, row, kc));
            }
#pragma unroll
            for (int gj = 0; gj < 4; gj++) {
                int row = wn * 64 + gj * 16 + (q >> 1) * 8 + sub;
                int kc = ks * 2 + (q & 1);
                ldsm_x4(bh[gj], sw_addr(bH, row, kc));
                ldsm_x4(bl[gj], sw_addr(bL, row, kc));
            }
#pragma unroll
            for (int mi = 0; mi < 4; mi++)
#pragma unroll
                for (int nj = 0; nj < 8; nj++) {
                    const uint32_t* ph = &bh[nj >> 1][(nj & 1) * 2];
                    const uint32_t* pl = &bl[nj >> 1][(nj & 1) * 2];
                    mma_16816(acc[mi][nj], ah[mi], ph);
                    mma_16816(acc[mi][nj], ah[mi], pl);
                    mma_16816(acc[mi][nj], al[mi], ph);
                }
        }
    }

    int qr = lane >> 2, qc = lane & 3;
#pragma unroll
    for (int mi = 0; mi < 4; mi++) {
#pragma unroll
        for (int half = 0; half < 2; half++) {
            int rl = wm * 64 + mi * 16 + half * 8 + qr;
            if (moe && mb + rl >= cnt) continue;
            if (mode == 6) {
                int grow = mb + rl;
#pragma unroll
                for (int nj = 0; nj < 8; nj++) {
                    float v0 = acc[mi][nj][half * 2 + 0];
                    float v1 = acc[mi][nj][half * 2 + 1];
                    int col = n0 + wn * 64 + qc * 2 + nj * 8;
                    if (n0 < 2048) {
                        *(float2*)&C[(size_t)grow * 2048 + col] = make_float2(v0, v1);
                    } else if (n0 < 2560) {
                        *(float2*)&g_k[(size_t)grow * 512 + col - 2048] = make_float2(v0, v1);
                    } else {
                        size_t a = (size_t)grow * 512 + col - 2560;
                        __nv_bfloat162 hv = __floats2bfloat162_rn(v0, v1);
                        *(__nv_bfloat162*)&g_v_hi[a] = hv;
                        *(__nv_bfloat162*)&g_v_lo[a] =
                            __floats2bfloat162_rn(v0 - __bfloat162float(hv.x),
                                                  v1 - __bfloat162float(hv.y));
                    }
                }
            } else if (mode == 4) {
                int entry = crowS[rl];
                float eg = g_entrygate[entry];
#pragma unroll
                for (int nj = 0; nj < 8; nj++) {
                    float gv = acc[mi][nj][half * 2 + 0];
                    float uv = acc[mi][nj][half * 2 + 1];
                    int f = (n0 + wn * 64 + qc * 2 + nj * 8) >> 1;
                    float a = eg * (gv / (1.f + __expf(-gv))) * uv;
                    size_t ai = (size_t)entry * NF + f;
                    split_store(a, g_act_hi + ai, g_act_lo + ai);
                }
            } else if (mode == 2) {
                size_t gbase = (size_t)(crowS[rl] >> 1) * N + n0 + wn * 64 + qc * 2;
#pragma unroll
                for (int nj = 0; nj < 8; nj++) {
                    atomicAdd(&C[gbase + nj * 8 + 0], acc[mi][nj][half * 2 + 0]);
                    atomicAdd(&C[gbase + nj * 8 + 1], acc[mi][nj][half * 2 + 1]);
                }
            } else {  // mode 0
                size_t gbase = (size_t)(mb + rl) * N + n0 + wn * 64 + qc * 2;
#pragma unroll
                for (int nj = 0; nj < 8; nj++) {
                    float v0 = acc[mi][nj][half * 2 + 0];
                    float v1 = acc[mi][nj][half * 2 + 1];
                    size_t addr = gbase + nj * 8;
                    if (resid) {
                        v0 += resid[addr + 0];
                        v1 += resid[addr + 1];
                    }
                    float2 st = make_float2(v0, v1);
                    *(float2*)&C[addr] = st;
                    if (aux) *(float2*)&aux[addr] = st;
                }
            }
        }
    }
}

// ---------------- host launch ----------------
extern "C" void kernel_launch(void* const* d_in, const int* in_sizes, int n_in,
                              void* d_out, int out_size) {
    const float* x          = (const float*)d_in[0];
    const float* wattn_norm = (const float*)d_in[1];
    const float* wq         = (const float*)d_in[2];
    const float* wk         = (const float*)d_in[3];
    const float* wv         = (const float*)d_in[4];
    const float* wq_norm    = (const float*)d_in[5];
    const float* wk_norm    = (const float*)d_in[6];
    const float* wattn_out  = (const float*)d_in[7];
    const float* wffn_norm  = (const float*)d_in[8];
    const float* w_router   = (const float*)d_in[9];
    const float* w_gate     = (const float*)d_in[10];
    const float* w_up       = (const float*)d_in[11];
    const float* w_down     = (const float*)d_in[12];
    float* out = (float*)d_out;

    cudaFuncSetAttribute(hmma_gemm, cudaFuncAttributeMaxDynamicSharedMemorySize, HM_SMEM);
    cudaFuncSetAttribute(attn_hmma, cudaFuncAttributeMaxDynamicSharedMemorySize, AT_SMEM);

    float *p_q, *p_k, *p_x2, *p_h2;
    cudaGetSymbolAddress((void**)&p_q, g_q);
    cudaGetSymbolAddress((void**)&p_k, g_k);
    cudaGetSymbolAddress((void**)&p_x2, g_x2);
    cudaGetSymbolAddress((void**)&p_h2, g_h2);

    __nv_bfloat16 *hh, *hl, *h2h, *h2l, *oh, *ol, *ah, *al;
    __nv_bfloat16 *kh_, *kl_, *vh_, *vl_;
    __nv_bfloat16 *wqkvh, *wqkvl, *woh, *wol, *wguh, *wgul, *wdh, *wdl;
    cudaGetSymbolAddress((void**)&hh, g_h_hi);   cudaGetSymbolAddress((void**)&hl, g_h_lo);
    cudaGetSymbolAddress((void**)&h2h, g_h2_hi); cudaGetSymbolAddress((void**)&h2l, g_h2_lo);
    cudaGetSymbolAddress((void**)&oh, g_o_hi);   cudaGetSymbolAddress((void**)&ol, g_o_lo);
    cudaGetSymbolAddress((void**)&ah, g_act_hi); cudaGetSymbolAddress((void**)&al, g_act_lo);
    cudaGetSymbolAddress((void**)&kh_, g_k_hi);  cudaGetSymbolAddress((void**)&kl_, g_k_lo);
    cudaGetSymbolAddress((void**)&vh_, g_v_hi);  cudaGetSymbolAddress((void**)&vl_, g_v_lo);
    cudaGetSymbolAddress((void**)&wqkvh, g_wqkv_hi); cudaGetSymbolAddress((void**)&wqkvl, g_wqkv_lo);
    cudaGetSymbolAddress((void**)&woh, g_wo_hi); cudaGetSymbolAddress((void**)&wol, g_wo_lo);
    cudaGetSymbolAddress((void**)&wguh, g_wgu_hi); cudaGetSymbolAddress((void**)&wgul, g_wgu_lo);
    cudaGetSymbolAddress((void**)&wdh, g_wd_hi); cudaGetSymbolAddress((void**)&wdl, g_wd_lo);

    // 0-2: QKV weight splits into packed buffer
    split_kernel<<<512, 256>>>((const float4*)wq, (__nv_bfloat162*)wqkvh, (__nv_bfloat162*)wqkvl, 2048 * 512);
    split_kernel<<<128, 256>>>((const float4*)wk, (__nv_bfloat162*)(wqkvh + 2048 * 2048),
                               (__nv_bfloat162*)(wqkvl + 2048 * 2048), 512 * 512);
    split_kernel<<<128, 256>>>((const float4*)wv, (__nv_bfloat162*)(wqkvh + 2560 * 2048),
                               (__nv_bfloat162*)(wqkvl + 2560 * 2048), 512 * 512);
    // 3: h = rmsnorm(x)
    rmsnorm_split<<<T_TOK, 256>>>(x, wattn_norm, nullptr, hh, hl);
    // 4: wo split
    split_kernel<<<512, 256>>>((const float4*)wattn_out, (__nv_bfloat162*)woh, (__nv_bfloat162*)wol, 2048 * 512);
    // 5: fused QKV projection (M-tile 256)
    hmma_gemm<<<dim3(24, 16, 1), 256, HM_SMEM>>>(hh, hl, wqkvh, wqkvl, p_q, 3072, 2048, nullptr, nullptr, 6);
    // 6-7: qk norm + rope (warp-per-head)
    qknorm_rope<<<T_TOK * NH / 8, 256>>>(p_q, wq_norm, NH, nullptr, nullptr);
    qknorm_rope<<<T_TOK * NKV / 8, 256>>>(p_k, wk_norm, NKV, kh_, kl_);
    // 8: HMMA flash attention -> o split
    attn_hmma<<<dim3(16, NH, 2), 256, AT_SMEM>>>(p_q, kh_, kl_, vh_, vl_, oh, ol);
    // 9: out projection + residual (writes g_x2 and d_out)
    hmma_gemm<<<dim3(16, 16, 1), 256, HM_SMEM>>>(oh, ol, woh, wol, p_x2, 2048, 2048, x, out, 0);
    // 10: h2 = rmsnorm(x2)
    rmsnorm_split<<<T_TOK, 256>>>(p_x2, wffn_norm, p_h2, h2h, h2l);
    // 11-12: router
    zero_cnt_kernel<<<1, NE>>>();
    router_kernel<<<T_TOK, 256>>>(p_h2, w_router);
    // 13-15: MoE weight splits
    split_interleave<<<1024, 256>>>((const float4*)w_gate, (__nv_bfloat162*)wguh, (__nv_bfloat162*)wgul, 0);
    split_interleave<<<1024, 256>>>((const float4*)w_up, (__nv_bfloat162*)wguh, (__nv_bfloat162*)wgul, 1);
    split_kernel<<<1024, 256>>>((const float4*)w_down, (__nv_bfloat162*)wdh, (__nv_bfloat162*)wdl, NE * D_MODEL * 256);
    // 16: fused gate/up GEMM + silu + router gate -> act split
    hmma_gemm<<<dim3(16, 32, NE), 256, HM_SMEM>>>(h2h, h2l, wguh, wgul, nullptr, 2048, 2048, nullptr, nullptr, 4);
    // 17: down projection, scatter-add into out
    hmma_gemm<<<dim3(16, 32, NE), 256, HM_SMEM>>>(ah, al, wdh, wdl, out, D_MODEL, NF, nullptr, nullptr, 2);
}

// round 11
// speedup vs baseline: 1.0603x; 1.0603x over previous
#include <cuda_runtime.h>
#include <cuda_bf16.h>
#include <math.h>
#include <stdint.h>

#define T_TOK 4096
#define D_MODEL 2048
#define S_SEQ 2048
#define NH 16
#define NKV 4
#define HDIM 128
#define NE 8
#define NF 1024
#define LIST_STRIDE (2 * T_TOK)

// ---------------- scratch (static device allocations; no cudaMalloc) ----------------
__device__ float g_q  [T_TOK * NH * HDIM];
__device__ float g_k  [T_TOK * NKV * HDIM];
__device__ float g_h2 [T_TOK * D_MODEL];
__device__ int   g_toklist[NE * LIST_STRIDE];
__device__ float g_entrygate[2 * T_TOK];
__device__ int   g_expcnt[NE];

// bf16 hi/lo split buffers
__device__ __nv_bfloat16 g_h_hi [T_TOK * D_MODEL],  g_h_lo [T_TOK * D_MODEL];
__device__ __nv_bfloat16 g_h2_hi[T_TOK * D_MODEL],  g_h2_lo[T_TOK * D_MODEL];
__device__ __nv_bfloat16 g_o_hi [T_TOK * D_MODEL],  g_o_lo [T_TOK * D_MODEL];
__device__ __nv_bfloat16 g_k_hi [T_TOK * NKV * HDIM], g_k_lo [T_TOK * NKV * HDIM];
__device__ __nv_bfloat16 g_v_hi [T_TOK * NKV * HDIM], g_v_lo [T_TOK * NKV * HDIM];
__device__ __nv_bfloat16 g_act_hi[T_TOK * 2 * NF],  g_act_lo[T_TOK * 2 * NF];
// packed QKV weights: rows 0..2047 wq, 2048..2559 wk, 2560..3071 wv
__device__ __nv_bfloat16 g_wqkv_hi[3072 * 2048], g_wqkv_lo[3072 * 2048];
__device__ __nv_bfloat16 g_wo_hi[2048 * 2048], g_wo_lo[2048 * 2048];
// interleaved gate/up: per expert 2048 rows, row 2f = wg[f], 2f+1 = wu[f]
__device__ __nv_bfloat16 g_wgu_hi[NE * 2048 * D_MODEL], g_wgu_lo[NE * 2048 * D_MODEL];
__device__ __nv_bfloat16 g_wd_hi[NE * D_MODEL * NF], g_wd_lo[NE * D_MODEL * NF];

// ---------------- PTX helpers ----------------
__device__ __forceinline__ uint32_t smem_u32(const void* p) {
    return (uint32_t)__cvta_generic_to_shared(p);
}
__device__ __forceinline__ void cpa16(uint32_t dst, const void* src) {
    asm volatile("cp.async.cg.shared.global [%0], [%1], 16;" :: "r"(dst), "l"(src));
}
__device__ __forceinline__ void cp_commit() { asm volatile("cp.async.commit_group;" ::: "memory"); }
__device__ __forceinline__ void cp_wait1()  { asm volatile("cp.async.wait_group 1;" ::: "memory"); }
__device__ __forceinline__ void cp_wait0()  { asm volatile("cp.async.wait_group 0;" ::: "memory"); }

__device__ __forceinline__ void ldsm_x4(uint32_t r[4], uint32_t addr) {
    asm volatile("ldmatrix.sync.aligned.m8n8.x4.shared.b16 {%0,%1,%2,%3}, [%4];"
                 : "=r"(r[0]), "=r"(r[1]), "=r"(r[2]), "=r"(r[3]) : "r"(addr));
}
__device__ __forceinline__ void ldsm_x4_t(uint32_t r[4], uint32_t addr) {
    asm volatile("ldmatrix.sync.aligned.m8n8.x4.trans.shared.b16 {%0,%1,%2,%3}, [%4];"
                 : "=r"(r[0]), "=r"(r[1]), "=r"(r[2]), "=r"(r[3]) : "r"(addr));
}
__device__ __forceinline__ void mma_16816(float acc[4], const uint32_t a[4], const uint32_t b[2]) {
    asm volatile(
        "mma.sync.aligned.m16n8k16.row.col.f32.bf16.bf16.f32 "
        "{%0,%1,%2,%3}, {%4,%5,%6,%7}, {%8,%9}, {%0,%1,%2,%3};"
        : "+f"(acc[0]), "+f"(acc[1]), "+f"(acc[2]), "+f"(acc[3])
        : "r"(a[0]), "r"(a[1]), "r"(a[2]), "r"(a[3]), "r"(b[0]), "r"(b[1]));
}
__device__ __forceinline__ void split_store(float v, __nv_bfloat16* hp, __nv_bfloat16* lp) {
    __nv_bfloat16 h = __float2bfloat16_rn(v);
    *hp = h;
    *lp = __float2bfloat16_rn(v - __bfloat162float(h));
}
__device__ __forceinline__ uint32_t bf2u(__nv_bfloat162 h) {
    uint32_t u;
    asm("mov.b32 %0, {%1, %2};" : "=r"(u)
        : "h"(__bfloat16_as_ushort(h.x)), "h"(__bfloat16_as_ushort(h.y)));
    return u;
}

// ---------------- fp32 -> bf16 hi/lo split (contiguous, 2x ILP) ----------------
__global__ void split_kernel(const float4* __restrict__ s, __nv_bfloat162* __restrict__ hi,
                             __nv_bfloat162* __restrict__ lo, int n4) {
    int i = (blockIdx.x * blockDim.x + threadIdx.x) * 2;
    int stride = gridDim.x * blockDim.x * 2;
    for (; i < n4; i += stride) {
        float4 v0 = s[i];
        float4 v1 = s[i + 1];
#pragma unroll
        for (int j = 0; j < 2; j++) {
            float4 v = j ? v1 : v0;
            int k = i + j;
            __nv_bfloat162 h0 = __floats2bfloat162_rn(v.x, v.y);
            __nv_bfloat162 h1 = __floats2bfloat162_rn(v.z, v.w);
            hi[k * 2 + 0] = h0;
            hi[k * 2 + 1] = h1;
            lo[k * 2 + 0] = __floats2bfloat162_rn(v.x - __bfloat162float(h0.x),
                                                  v.y - __bfloat162float(h0.y));
            lo[k * 2 + 1] = __floats2bfloat162_rn(v.z - __bfloat162float(h1.x),
                                                  v.w - __bfloat162float(h1.y));
        }
    }
}

// ---------------- gate/up interleaving split: src (e,f,d) -> dst row e*2048 + 2f + sel ----
__global__ void split_interleave(const float4* __restrict__ s, __nv_bfloat162* __restrict__ hi,
                                 __nv_bfloat162* __restrict__ lo, int sel) {
    int n4 = NE * NF * (D_MODEL / 4);
    int i = (blockIdx.x * blockDim.x + threadIdx.x) * 2;
    int stride = gridDim.x * blockDim.x * 2;
    for (; i < n4; i += stride) {
        float4 v0 = s[i];
        float4 v1 = s[i + 1];
#pragma unroll
        for (int j = 0; j < 2; j++) {
            float4 v = j ? v1 : v0;
            int k = i + j;
            int d4 = k & 511;
            int fidx = k >> 9;
            int f = fidx & (NF - 1);
            int e = fidx >> 10;
            size_t dst2 = ((size_t)(e * 2048 + 2 * f + sel) * 512 + d4) * 2;
            __nv_bfloat162 h0 = __floats2bfloat162_rn(v.x, v.y);
            __nv_bfloat162 h1 = __floats2bfloat162_rn(v.z, v.w);
            hi[dst2 + 0] = h0;
            hi[dst2 + 1] = h1;
            lo[dst2 + 0] = __floats2bfloat162_rn(v.x - __bfloat162float(h0.x),
                                                 v.y - __bfloat162float(h0.y));
            lo[dst2 + 1] = __floats2bfloat162_rn(v.z - __bfloat162float(h1.x),
                                                 v.w - __bfloat162float(h1.y));
        }
    }
}

// ---------------- rmsnorm + split (optionally zeroes expert counters) ----------------
__global__ void rmsnorm_split(const float* __restrict__ x, const float* __restrict__ w,
                              float* __restrict__ outf, __nv_bfloat16* __restrict__ hi,
                              __nv_bfloat16* __restrict__ lo, int zflag) {
    int row = blockIdx.x;
    int tid = threadIdx.x;  // 256
    if (zflag && row == 0 && tid < NE) g_expcnt[tid] = 0;
    const float* xr = x + (size_t)row * D_MODEL;
    float xv[8];
    float ss = 0.f;
#pragma unroll
    for (int i = 0; i < 8; i++) {
        xv[i] = xr[tid + i * 256];
        ss += xv[i] * xv[i];
    }
#pragma unroll
    for (int o = 16; o > 0; o >>= 1) ss += __shfl_xor_sync(0xffffffffu, ss, o);
    __shared__ float sred[8];
    if ((tid & 31) == 0) sred[tid >> 5] = ss;
    __syncthreads();
    float tot = 0.f;
#pragma unroll
    for (int i = 0; i < 8; i++) tot += sred[i];
    float rs = rsqrtf(tot / (float)D_MODEL + 1e-6f);
    size_t base = (size_t)row * D_MODEL;
#pragma unroll
    for (int i = 0; i < 8; i++) {
        int d = tid + i * 256;
        float v = xv[i] * rs * w[d];
        if (outf) outf[base + d] = v;
        split_store(v, hi + base + d, lo + base + d);
    }
}

// ---------------- per-head rmsnorm + RoPE: one WARP per head ----------------
__global__ void qknorm_rope(float* __restrict__ data, const float* __restrict__ w, int nheads,
                            __nv_bfloat16* __restrict__ hi, __nv_bfloat16* __restrict__ lo) {
    int gw = blockIdx.x * 8 + (threadIdx.x >> 5);
    int lane = threadIdx.x & 31;
    int t = gw / nheads;
    int h = gw - t * nheads;
    size_t off = ((size_t)t * nheads + h) * HDIM + lane * 4;
    float4 v = *(float4*)&data[off];
    float ss = v.x * v.x + v.y * v.y + v.z * v.z + v.w * v.w;
#pragma unroll
    for (int o = 16; o > 0; o >>= 1) ss += __shfl_xor_sync(0xffffffffu, ss, o);
    float rs = rsqrtf(ss * (1.f / 128.f) + 1e-6f);
    const float4 wv = *(const float4*)&w[lane * 4];
    v.x *= rs * wv.x; v.y *= rs * wv.y; v.z *= rs * wv.z; v.w *= rs * wv.w;
    float4 p;
    p.x = __shfl_xor_sync(0xffffffffu, v.x, 16);
    p.y = __shfl_xor_sync(0xffffffffu, v.y, 16);
    p.z = __shfl_xor_sync(0xffffffffu, v.z, 16);
    p.w = __shfl_xor_sync(0xffffffffu, v.w, 16);
    int s = t & (S_SEQ - 1);
    int ibase = (lane * 4) & 63;
    bool lohalf = lane < 16;
    float o4[4];
    float vv[4] = {v.x, v.y, v.z, v.w};
    float pp[4] = {p.x, p.y, p.z, p.w};
#pragma unroll
    for (int c = 0; c < 4; c++) {
        float fi = exp2f(-(float)(ibase + c) * 0.20762050592154265f);
        float ang = (float)s * fi;
        float sn, cs;
        sincosf(ang, &sn, &cs);
        o4[c] = lohalf ? (vv[c] * cs - pp[c] * sn) : (pp[c] * sn + vv[c] * cs);
    }
    if (hi) {
#pragma unroll
        for (int c = 0; c < 4; c++) split_store(o4[c], hi + off + c, lo + off + c);
    } else {
        *(float4*)&data[off] = make_float4(o4[0], o4[1], o4[2], o4[3]);
    }
}

// ---------------- HMMA causal flash attention ----------------
#define AT_SMEM (65536 + 2 * 65536)

__device__ __forceinline__ uint32_t tile_addr(uint32_t base, int row, int chunk) {
    return base + (uint32_t)(row * 256) + (uint32_t)((chunk ^ (row & 7)) << 4);
}

__global__ __launch_bounds__(256, 1) void attn_hmma(
    const float* __restrict__ Q,
    const __nv_bfloat16* __restrict__ Kh, const __nv_bfloat16* __restrict__ Kl,
    const __nv_bfloat16* __restrict__ Vh, const __nv_bfloat16* __restrict__ Vl,
    __nv_bfloat16* __restrict__ Ohi, __nv_bfloat16* __restrict__ Olo) {
    extern __shared__ char dsm[];
    uint32_t sb = smem_u32(dsm);
    const uint32_t Qh_s = sb, Ql_s = sb + 32768u;
    int qb = 15 - (int)blockIdx.x;
    int h = blockIdx.y, b = blockIdx.z;
    int tid = threadIdx.x;
    int w = tid >> 5, lane = tid & 31;
    int kvh = h >> 2;
    int qg = lane >> 3, sub = lane & 7;
    int qr = lane >> 2, qc2 = (lane & 3) * 2;
    const float e2 = 0.12751743f;  // log2(e)/sqrt(128)

#pragma unroll
    for (int i = 0; i < 16; i++) {
        int idx = i * 256 + tid;
        int row = idx >> 5;
        int d4 = (idx & 31) * 4;
        const float4 v = *(const float4*)&Q[(((size_t)(b * S_SEQ + qb * 128 + row) * NH + h) << 7) + d4];
        __nv_bfloat162 h0 = __floats2bfloat162_rn(v.x, v.y);
        __nv_bfloat162 h1 = __floats2bfloat162_rn(v.z, v.w);
        __nv_bfloat162 l0v = __floats2bfloat162_rn(v.x - __bfloat162float(h0.x),
                                                   v.y - __bfloat162float(h0.y));
        __nv_bfloat162 l1v = __floats2bfloat162_rn(v.z - __bfloat162float(h1.x),
                                                   v.w - __bfloat162float(h1.y));
        uint32_t a = (uint32_t)(row * 256 + (((d4 >> 3) ^ (row & 7)) << 4) + (d4 & 7) * 2);
        *(__nv_bfloat162*)(dsm + a) = h0;
        *(__nv_bfloat162*)(dsm + a + 4) = h1;
        *(__nv_bfloat162*)(dsm + 32768 + a) = l0v;
        *(__nv_bfloat162*)(dsm + 32768 + a + 4) = l1v;
    }

    auto prefetch = [&](int kb, int buf) {
        uint32_t base = sb + 65536u + (uint32_t)buf * 65536u;
#pragma unroll
        for (int i = 0; i < 16; i++) {
            int ci = i * 256 + tid;
            int mat = ci >> 10;
            int idx = ci & 1023;
            int row = idx >> 4, chunk = idx & 15;
            uint32_t dst = tile_addr(base + (uint32_t)mat * 16384u, row, chunk);
            size_t goff = (((size_t)(b * S_SEQ + kb * 64 + row) * NKV + kvh) << 7) + chunk * 8;
            const __nv_bfloat16* src;
            if (mat == 0) src = Kh + goff;
            else if (mat == 1) src = Kl + goff;
            else if (mat == 2) src = Vh + goff;
            else src = Vl + goff;
            cpa16(dst, src);
        }
        cp_commit();
    };

    float Oa[16][4];
#pragma unroll
    for (int d = 0; d < 16; d++)
#pragma unroll
        for (int j = 0; j < 4; j++) Oa[d][j] = 0.f;
    float m0 = -1e30f, m1 = -1e30f, l0 = 0.f, l1 = 0.f;

    int nkb = 2 * qb + 2;
    prefetch(0, 0);

    for (int kb = 0; kb < nkb; kb++) {
        cp_wait0();
        __syncthreads();
        if (kb + 1 < nkb) prefetch(kb + 1, (kb + 1) & 1);
        uint32_t kv = sb + 65536u + (uint32_t)(kb & 1) * 65536u;
        uint32_t Kh_t = kv, Kl_t = kv + 16384u, Vh_t = kv + 32768u, Vl_t = kv + 49152u;

        float s[8][4];
#pragma unroll
        for (int nb = 0; nb < 8; nb++)
#pragma unroll
            for (int j = 0; j < 4; j++) s[nb][j] = 0.f;

#pragma unroll
        for (int kc = 0; kc < 8; kc++) {
            uint32_t ah[4], al[4];
            int arow = w * 16 + (qg & 1) * 8 + sub;
            int achk = kc * 2 + (qg >> 1);
            ldsm_x4(ah, tile_addr(Qh_s, arow, achk));
            ldsm_x4(al, tile_addr(Ql_s, arow, achk));
#pragma unroll
            for (int nbp = 0; nbp < 4; nbp++) {
                uint32_t bh[4], bl[4];
                int brow = nbp * 16 + (qg >> 1) * 8 + sub;
                int bchk = kc * 2 + (qg & 1);
                ldsm_x4(bh, tile_addr(Kh_t, brow, bchk));
                ldsm_x4(bl, tile_addr(Kl_t, brow, bchk));
                mma_16816(s[2 * nbp + 0], ah, bh + 0);
                mma_16816(s[2 * nbp + 0], ah, bl + 0);
                mma_16816(s[2 * nbp + 0], al, bh + 0);
                mma_16816(s[2 * nbp + 1], ah, bh + 2);
                mma_16816(s[2 * nbp + 1], ah, bl + 2);
                mma_16816(s[2 * nbp + 1], al, bh + 2);
            }
        }

        int row0 = qb * 128 + w * 16 + qr;
        int row1 = row0 + 8;
        if (kb >= 2 * qb) {
            int colb = kb * 64 + qc2;
#pragma unroll
            for (int nb = 0; nb < 8; nb++) {
                int c0 = colb + nb * 8, c1 = c0 + 1;
                if (c0 > row0) s[nb][0] = -1e30f;
                if (c1 > row0) s[nb][1] = -1e30f;
                if (c0 > row1) s[nb][2] = -1e30f;
                if (c1 > row1) s[nb][3] = -1e30f;
            }
        }
        float mx0 = -1e30f, mx1 = -1e30f;
#pragma unroll
        for (int nb = 0; nb < 8; nb++) {
            mx0 = fmaxf(mx0, fmaxf(s[nb][0], s[nb][1]));
            mx1 = fmaxf(mx1, fmaxf(s[nb][2], s[nb][3]));
        }
        mx0 = fmaxf(mx0, __shfl_xor_sync(0xffffffffu, mx0, 1));
        mx0 = fmaxf(mx0, __shfl_xor_sync(0xffffffffu, mx0, 2));
        mx1 = fmaxf(mx1, __shfl_xor_sync(0xffffffffu, mx1, 1));
        mx1 = fmaxf(mx1, __shfl_xor_sync(0xffffffffu, mx1, 2));
        float mn0 = fmaxf(m0, mx0), mn1 = fmaxf(m1, mx1);
        float f0 = exp2f((m0 - mn0) * e2), f1 = exp2f((m1 - mn1) * e2);
        m0 = mn0; m1 = mn1;
        l0 *= f0; l1 *= f1;
#pragma unroll
        for (int d = 0; d < 16; d++) {
            Oa[d][0] *= f0; Oa[d][1] *= f0;
            Oa[d][2] *= f1; Oa[d][3] *= f1;
        }
#pragma unroll
        for (int nb = 0; nb < 8; nb++) {
            s[nb][0] = exp2f((s[nb][0] - mn0) * e2);
            s[nb][1] = exp2f((s[nb][1] - mn0) * e2);
            s[nb][2] = exp2f((s[nb][2] - mn1) * e2);
            s[nb][3] = exp2f((s[nb][3] - mn1) * e2);
            l0 += s[nb][0] + s[nb][1];
            l1 += s[nb][2] + s[nb][3];
        }

#pragma unroll
        for (int kk = 0; kk < 4; kk++) {
            uint32_t ph[4], pl[4];
            float* p0 = s[2 * kk];
            float* p1 = s[2 * kk + 1];
            __nv_bfloat162 h00 = __floats2bfloat162_rn(p0[0], p0[1]);
            __nv_bfloat162 h01 = __floats2bfloat162_rn(p0[2], p0[3]);
            __nv_bfloat162 h10 = __floats2bfloat162_rn(p1[0], p1[1]);
            __nv_bfloat162 h11 = __floats2bfloat162_rn(p1[2], p1[3]);
            ph[0] = bf2u(h00); ph[1] = bf2u(h01);
            ph[2] = bf2u(h10); ph[3] = bf2u(h11);
            pl[0] = bf2u(__floats2bfloat162_rn(p0[0] - __bfloat162float(h00.x),
                                               p0[1] - __bfloat162float(h00.y)));
            pl[1] = bf2u(__floats2bfloat162_rn(p0[2] - __bfloat162float(h01.x),
                                               p0[3] - __bfloat162float(h01.y)));
            pl[2] = bf2u(__floats2bfloat162_rn(p1[0] - __bfloat162float(h10.x),
                                               p1[1] - __bfloat162float(h10.y)));
            pl[3] = bf2u(__floats2bfloat162_rn(p1[2] - __bfloat162float(h11.x),
                                               p1[3] - __bfloat162float(h11.y)));
#pragma unroll
            for (int dbp = 0; dbp < 8; dbp++) {
                uint32_t vh[4], vl[4];
                int vrow = kk * 16 + (qg & 1) * 8 + sub;
                int vchk = dbp * 2 + (qg >> 1);
                ldsm_x4_t(vh, tile_addr(Vh_t, vrow, vchk));
                ldsm_x4_t(vl, tile_addr(Vl_t, vrow, vchk));
                mma_16816(Oa[2 * dbp + 0], ph, vh + 0);
                mma_16816(Oa[2 * dbp + 0], ph, vl + 0);
                mma_16816(Oa[2 * dbp + 0], pl, vh + 0);
                mma_16816(Oa[2 * dbp + 1], ph, vh + 2);
                mma_16816(Oa[2 * dbp + 1], ph, vl + 2);
                mma_16816(Oa[2 * dbp + 1], pl, vh + 2);
            }
        }
    }

    l0 += __shfl_xor_sync(0xffffffffu, l0, 1);
    l0 += __shfl_xor_sync(0xffffffffu, l0, 2);
    l1 += __shfl_xor_sync(0xffffffffu, l1, 1);
    l1 += __shfl_xor_sync(0xffffffffu, l1, 2);
    float i0 = 1.f / l0, i1 = 1.f / l1;
    int row0 = qb * 128 + w * 16 + qr;
#pragma unroll
    for (int db = 0; db < 16; db++) {
        int col = h * 128 + db * 8 + qc2;
        size_t a0 = ((size_t)(b * S_SEQ + row0) << 11) + col;
        size_t a1 = ((size_t)(b * S_SEQ + row0 + 8) << 11) + col;
        float v0 = Oa[db][0] * i0, v1 = Oa[db][1] * i0;
        float v2 = Oa[db][2] * i1, v3 = Oa[db][3] * i1;
        __nv_bfloat162 h0 = __floats2bfloat162_rn(v0, v1);
        __nv_bfloat162 h1 = __floats2bfloat162_rn(v2, v3);
        *(__nv_bfloat162*)&Ohi[a0] = h0;
        *(__nv_bfloat162*)&Ohi[a1] = h1;
        *(__nv_bfloat162*)&Olo[a0] = __floats2bfloat162_rn(v0 - __bfloat162float(h0.x),
                                                           v1 - __bfloat162float(h0.y));
        *(__nv_bfloat162*)&Olo[a1] = __floats2bfloat162_rn(v2 - __bfloat162float(h1.x),
                                                           v3 - __bfloat162float(h1.y));
    }
}

// ---------------- router ----------------
__global__ void router_kernel(const float* __restrict__ h2, const float* __restrict__ wr) {
    int t = blockIdx.x;
    int tid = threadIdx.x;  // 256
    float p[8];
#pragma unroll
    for (int e = 0; e < 8; e++) p[e] = 0.f;
#pragma unroll
    for (int i = 0; i < 8; i++) {
        int d = tid + i * 256;
        float hv = h2[(size_t)t * D_MODEL + d];
#pragma unroll
        for (int e = 0; e < 8; e++) p[e] += hv * wr[e * D_MODEL + d];
    }
    __shared__ float red[8][256];
#pragma unroll
    for (int e = 0; e < 8; e++) red[e][tid] = p[e];
    __syncthreads();
    for (int stp = 128; stp > 0; stp >>= 1) {
        if (tid < stp) {
#pragma unroll
            for (int e = 0; e < 8; e++) red[e][tid] += red[e][tid + stp];
        }
        __syncthreads();
    }
    if (tid == 0) {
        float lg[8];
        float m = -1e30f;
#pragma unroll
        for (int e = 0; e < 8; e++) { lg[e] = red[e][0]; m = fmaxf(m, lg[e]); }
        float pr[8];
#pragma unroll
        for (int e = 0; e < 8; e++) pr[e] = __expf(lg[e] - m);
        int i1 = 0;
#pragma unroll
        for (int e = 1; e < 8; e++) if (pr[e] > pr[i1]) i1 = e;
        int i2 = (i1 == 0) ? 1 : 0;
#pragma unroll
        for (int e = 0; e < 8; e++) if (e != i1 && pr[e] > pr[i2]) i2 = e;
        float v1 = pr[i1], v2 = pr[i2];
        float denom = v1 + v2;
        int pos1 = atomicAdd(&g_expcnt[i1], 1);
        g_toklist[i1 * LIST_STRIDE + pos1] = t * 2;
        g_entrygate[t * 2] = v1 / denom;
        int pos2 = atomicAdd(&g_expcnt[i2], 1);
        g_toklist[i2 * LIST_STRIDE + pos2] = t * 2 + 1;
        g_entrygate[t * 2 + 1] = v2 / denom;
    }
}

// ---------------- HMMA bf16x3 GEMM: C[M,N] = A @ B^T (R8 proven config) ----------------
// CTA tile 128x128, BK=32, 8 warps (2x4), warp tile 64x32, 3-stage, single sync.
// modes: 0 dense fp32 (+resid), 2 MoE-down atomic, 4 MoE gate/up interleaved + silu,
// 6 fused QKV epilogue (Q fp32 / K fp32 / V split).
#define STAGE_BYTES 32768
#define HM_SMEM (3 * STAGE_BYTES)

__device__ __forceinline__ uint32_t sw_addr(uint32_t base, int row, int kchunk) {
    return base + (uint32_t)(row * 64) + (uint32_t)((kchunk ^ ((row >> 1) & 3)) << 4);
}

__global__ __launch_bounds__(256) void hmma_gemm(
    const __nv_bfloat16* __restrict__ Ahi, const __nv_bfloat16* __restrict__ Alo,
    const __nv_bfloat16* __restrict__ Bhi, const __nv_bfloat16* __restrict__ Blo,
    float* __restrict__ C, int N, int K,
    const float* __restrict__ resid, int mode) {
    extern __shared__ char dsm[];
    __shared__ int arowS[128];
    __shared__ int crowS[128];

    int tid = threadIdx.x;
    int n0 = blockIdx.x * 128;
    int mb = blockIdx.y * 128;
    int e = blockIdx.z;
    int cnt = 1 << 30;
    bool moe = (mode == 2 || mode == 4);
    if (moe) {
        cnt = g_expcnt[e];
        if (mb >= cnt) return;
        size_t boff = (size_t)e * N * K;
        Bhi += boff;
        Blo += boff;
    }
    if (tid < 128) {
        if (moe) {
            int idx = mb + tid;
            if (idx > cnt - 1) idx = cnt - 1;
            int entry = g_toklist[e * LIST_STRIDE + idx];
            crowS[tid] = entry;
            arowS[tid] = (mode == 4) ? (entry >> 1) : entry;
        } else {
            arowS[tid] = mb + tid;
            crowS[tid] = mb + tid;
        }
    }
    __syncthreads();

    uint32_t sb = smem_u32(dsm);
    const __nv_bfloat16* mats[4] = {Ahi, Alo, Bhi, Blo};

    auto load_tile = [&](int stage, int k0) {
        uint32_t sbase = sb + (uint32_t)stage * STAGE_BYTES;
#pragma unroll
        for (int i = 0; i < 8; i++) {
            int ci = i * 256 + tid;
            int mat = ci >> 9;
            int idx = ci & 511;
            int r = idx >> 2, c = idx & 3;
            uint32_t dst = sw_addr(sbase + (uint32_t)mat * 8192u, r, c);
            int grow = (mat < 2) ? arowS[r] : (n0 + r);
            const __nv_bfloat16* src = mats[mat] + (size_t)grow * K + k0 + c * 8;
            cpa16(dst, src);
        }
        cp_commit();
    };

    int T = K >> 5;
    load_tile(0, 0);
    load_tile(1, 32);

    int warp = tid >> 5, lane = tid & 31;
    int wm = warp >> 2, wn = warp & 3;
    int q = lane >> 3, sub = lane & 7;

    float acc[4][4][4];
#pragma unroll
    for (int mi = 0; mi < 4; mi++)
#pragma unroll
        for (int nj = 0; nj < 4; nj++)
#pragma unroll
            for (int v = 0; v < 4; v++) acc[mi][nj][v] = 0.f;

    for (int kt = 0; kt < T; kt++) {
        if (kt < T - 1) cp_wait1(); else cp_wait0();
        __syncthreads();
        if (kt + 2 < T) load_tile((kt + 2) % 3, (kt + 2) * 32);
        uint32_t sbase = sb + (uint32_t)(kt % 3) * STAGE_BYTES;
        uint32_t aH = sbase, aL = sbase + 8192u, bH = sbase + 16384u, bL = sbase + 24576u;
#pragma unroll
        for (int ks = 0; ks < 2; ks++) {
            uint32_t ah[4][4], al[4][4], bh[2][4], bl[2][4];
#pragma unroll
            for (int mi = 0; mi < 4; mi++) {
                int row = wm * 64 + mi * 16 + (q & 1) * 8 + sub;
                int kc = ks * 2 + (q >> 1);
                ldsm_x4(ah[mi], sw_addr(aH, row, kc));
                ldsm_x4(al[mi], sw_addr(aL, row, kc));
            }
#pragma unroll
            for (int gj = 0; gj < 2; gj++) {
                int row = wn * 32 + gj * 16 + (q >> 1) * 8 + sub;
                int kc = ks * 2 + (q & 1);
                ldsm_x4(bh[gj], sw_addr(bH, row, kc));
                ldsm_x4(bl[gj], sw_addr(bL, row, kc));
            }
#pragma unroll
            for (int mi = 0; mi < 4; mi++)
#pragma unroll
                for (int nj = 0; nj < 4; nj++) {
                    const uint32_t* ph = &bh[nj >> 1][(nj & 1) * 2];
                    const uint32_t* pl = &bl[nj >> 1][(nj & 1) * 2];
                    mma_16816(acc[mi][nj], ah[mi], ph);
                    mma_16816(acc[mi][nj], ah[mi], pl);
                    mma_16816(acc[mi][nj], al[mi], ph);
                }
        }
    }

    int qr = lane >> 2, qc = lane & 3;
#pragma unroll
    for (int mi = 0; mi < 4; mi++) {
#pragma unroll
        for (int half = 0; half < 2; half++) {
            int rl = wm * 64 + mi * 16 + half * 8 + qr;
            if (moe && mb + rl >= cnt) continue;
            if (mode == 6) {
                int grow = mb + rl;
#pragma unroll
                for (int nj = 0; nj < 4; nj++) {
                    float v0 = acc[mi][nj][half * 2 + 0];
                    float v1 = acc[mi][nj][half * 2 + 1];
                    int col = n0 + wn * 32 + qc * 2 + nj * 8;
                    if (n0 < 2048) {
                        *(float2*)&C[(size_t)grow * 2048 + col] = make_float2(v0, v1);
                    } else if (n0 < 2560) {
                        *(float2*)&g_k[(size_t)grow * 512 + col - 2048] = make_float2(v0, v1);
                    } else {
                        size_t a = (size_t)grow * 512 + col - 2560;
                        __nv_bfloat162 hv = __floats2bfloat162_rn(v0, v1);
                        *(__nv_bfloat162*)&g_v_hi[a] = hv;
                        *(__nv_bfloat162*)&g_v_lo[a] =
                            __floats2bfloat162_rn(v0 - __bfloat162float(hv.x),
                                                  v1 - __bfloat162float(hv.y));
                    }
                }
            } else if (mode == 4) {
                int entry = crowS[rl];
                float eg = g_entrygate[entry];
#pragma unroll
                for (int nj = 0; nj < 4; nj++) {
                    float gv = acc[mi][nj][half * 2 + 0];
                    float uv = acc[mi][nj][half * 2 + 1];
                    int f = (n0 + wn * 32 + qc * 2 + nj * 8) >> 1;
                    float a = eg * (gv / (1.f + __expf(-gv))) * uv;
                    size_t ai = (size_t)entry * NF + f;
                    split_store(a, g_act_hi + ai, g_act_lo + ai);
                }
            } else if (mode == 2) {
                size_t gbase = (size_t)(crowS[rl] >> 1) * N + n0 + wn * 32 + qc * 2;
#pragma unroll
                for (int nj = 0; nj < 4; nj++) {
                    atomicAdd(&C[gbase + nj * 8 + 0], acc[mi][nj][half * 2 + 0]);
                    atomicAdd(&C[gbase + nj * 8 + 1], acc[mi][nj][half * 2 + 1]);
                }
            } else {  // mode 0
                size_t gbase = (size_t)(mb + rl) * N + n0 + wn * 32 + qc * 2;
#pragma unroll
                for (int nj = 0; nj < 4; nj++) {
                    float v0 = acc[mi][nj][half * 2 + 0];
                    float v1 = acc[mi][nj][half * 2 + 1];
                    size_t addr = gbase + nj * 8;
                    if (resid) {
                        v0 += resid[addr + 0];
                        v1 += resid[addr + 1];
                    }
                    *(float2*)&C[addr] = make_float2(v0, v1);
                }
            }
        }
    }
}

// ---------------- host launch ----------------
extern "C" void kernel_launch(void* const* d_in, const int* in_sizes, int n_in,
                              void* d_out, int out_size) {
    const float* x          = (const float*)d_in[0];
    const float* wattn_norm = (const float*)d_in[1];
    const float* wq         = (const float*)d_in[2];
    const float* wk         = (const float*)d_in[3];
    const float* wv         = (const float*)d_in[4];
    const float* wq_norm    = (const float*)d_in[5];
    const float* wk_norm    = (const float*)d_in[6];
    const float* wattn_out  = (const float*)d_in[7];
    const float* wffn_norm  = (const float*)d_in[8];
    const float* w_router   = (const float*)d_in[9];
    const float* w_gate     = (const float*)d_in[10];
    const float* w_up       = (const float*)d_in[11];
    const float* w_down     = (const float*)d_in[12];
    float* out = (float*)d_out;

    cudaFuncSetAttribute(hmma_gemm, cudaFuncAttributeMaxDynamicSharedMemorySize, HM_SMEM);
    cudaFuncSetAttribute(attn_hmma, cudaFuncAttributeMaxDynamicSharedMemorySize, AT_SMEM);

    float *p_q, *p_k, *p_h2;
    cudaGetSymbolAddress((void**)&p_q, g_q);
    cudaGetSymbolAddress((void**)&p_k, g_k);
    cudaGetSymbolAddress((void**)&p_h2, g_h2);

    __nv_bfloat16 *hh, *hl, *h2h, *h2l, *oh, *ol, *ah, *al;
    __nv_bfloat16 *kh_, *kl_, *vh_, *vl_;
    __nv_bfloat16 *wqkvh, *wqkvl, *woh, *wol, *wguh, *wgul, *wdh, *wdl;
    cudaGetSymbolAddress((void**)&hh, g_h_hi);   cudaGetSymbolAddress((void**)&hl, g_h_lo);
    cudaGetSymbolAddress((void**)&h2h, g_h2_hi); cudaGetSymbolAddress((void**)&h2l, g_h2_lo);
    cudaGetSymbolAddress((void**)&oh, g_o_hi);   cudaGetSymbolAddress((void**)&ol, g_o_lo);
    cudaGetSymbolAddress((void**)&ah, g_act_hi); cudaGetSymbolAddress((void**)&al, g_act_lo);
    cudaGetSymbolAddress((void**)&kh_, g_k_hi);  cudaGetSymbolAddress((void**)&kl_, g_k_lo);
    cudaGetSymbolAddress((void**)&vh_, g_v_hi);  cudaGetSymbolAddress((void**)&vl_, g_v_lo);
    cudaGetSymbolAddress((void**)&wqkvh, g_wqkv_hi); cudaGetSymbolAddress((void**)&wqkvl, g_wqkv_lo);
    cudaGetSymbolAddress((void**)&woh, g_wo_hi); cudaGetSymbolAddress((void**)&wol, g_wo_lo);
    cudaGetSymbolAddress((void**)&wguh, g_wgu_hi); cudaGetSymbolAddress((void**)&wgul, g_wgu_lo);
    cudaGetSymbolAddress((void**)&wdh, g_wd_hi); cudaGetSymbolAddress((void**)&wdl, g_wd_lo);

    // QKV weight splits into packed buffer
    split_kernel<<<512, 256>>>((const float4*)wq, (__nv_bfloat162*)wqkvh, (__nv_bfloat162*)wqkvl, 2048 * 512);
    split_kernel<<<128, 256>>>((const float4*)wk, (__nv_bfloat162*)(wqkvh + 2048 * 2048),
                               (__nv_bfloat162*)(wqkvl + 2048 * 2048), 512 * 512);
    split_kernel<<<128, 256>>>((const float4*)wv, (__nv_bfloat162*)(wqkvh + 2560 * 2048),
                               (__nv_bfloat162*)(wqkvl + 2560 * 2048), 512 * 512);
    // h = rmsnorm(x)
    rmsnorm_split<<<T_TOK, 256>>>(x, wattn_norm, nullptr, hh, hl, 0);
    // wo split
    split_kernel<<<512, 256>>>((const float4*)wattn_out, (__nv_bfloat162*)woh, (__nv_bfloat162*)wol, 2048 * 512);
    // fused QKV projection
    hmma_gemm<<<dim3(24, 32, 1), 256, HM_SMEM>>>(hh, hl, wqkvh, wqkvl, p_q, 3072, 2048, nullptr, 6);
    // qk norm + rope (warp-per-head)
    qknorm_rope<<<T_TOK * NH / 8, 256>>>(p_q, wq_norm, NH, nullptr, nullptr);
    qknorm_rope<<<T_TOK * NKV / 8, 256>>>(p_k, wk_norm, NKV, kh_, kl_);
    // HMMA flash attention -> o split
    attn_hmma<<<dim3(16, NH, 2), 256, AT_SMEM>>>(p_q, kh_, kl_, vh_, vl_, oh, ol);
    // out projection + residual -> d_out only (x2 == out)
    hmma_gemm<<<dim3(16, 32, 1), 256, HM_SMEM>>>(oh, ol, woh, wol, out, 2048, 2048, x, 0);
    // h2 = rmsnorm(out)  (+ zero expert counters)
    rmsnorm_split<<<T_TOK, 256>>>(out, wffn_norm, p_h2, h2h, h2l, 1);
    // router
    router_kernel<<<T_TOK, 256>>>(p_h2, w_router);
    // MoE weight splits
    split_interleave<<<1024, 256>>>((const float4*)w_gate, (__nv_bfloat162*)wguh, (__nv_bfloat162*)wgul, 0);
    split_interleave<<<1024, 256>>>((const float4*)w_up, (__nv_bfloat162*)wguh, (__nv_bfloat162*)wgul, 1);
    split_kernel<<<1024, 256>>>((const float4*)w_down, (__nv_bfloat162*)wdh, (__nv_bfloat162*)wdl, NE * D_MODEL * 256);
    // fused gate/up GEMM + silu + router gate -> act split
    hmma_gemm<<<dim3(16, 64, NE), 256, HM_SMEM>>>(h2h, h2l, wguh, wgul, nullptr, 2048, 2048, nullptr, 4);
    // down projection, scatter-add into out
    hmma_gemm<<<dim3(16, 64, NE), 256, HM_SMEM>>>(ah, al, wdh, wdl, out, D_MODEL, NF, nullptr, 2);
}

// round 13
// speedup vs baseline: 1.3548x; 1.2777x over previous
#include <cuda_runtime.h>
#include <cuda_bf16.h>
#include <cuda_fp16.h>
#include <math.h>
#include <stdint.h>

#define T_TOK 4096
#define D_MODEL 2048
#define S_SEQ 2048
#define NH 16
#define NKV 4
#define HDIM 128
#define NE 8
#define NF 1024
#define LIST_STRIDE (2 * T_TOK)

// ---------------- scratch (static device allocations; no cudaMalloc) ----------------
__device__ float g_q  [T_TOK * NH * HDIM];
__device__ float g_k  [T_TOK * NKV * HDIM];
__device__ float g_h2 [T_TOK * D_MODEL];
__device__ int   g_toklist[NE * LIST_STRIDE];
__device__ float g_entrygate[2 * T_TOK];
__device__ int   g_expcnt[NE];

// fp16 activation hi/lo splits (GEMM A operands)
__device__ __half g_h_hi [T_TOK * D_MODEL],  g_h_lo [T_TOK * D_MODEL];
__device__ __half g_h2_hi[T_TOK * D_MODEL],  g_h2_lo[T_TOK * D_MODEL];
__device__ __half g_o_hi [T_TOK * D_MODEL],  g_o_lo [T_TOK * D_MODEL];
__device__ __half g_act_hi[T_TOK * 2 * NF],  g_act_lo[T_TOK * 2 * NF];
// attention K/V stay bf16 hi/lo (proven kernel untouched)
__device__ __nv_bfloat16 g_k_hi [T_TOK * NKV * HDIM], g_k_lo [T_TOK * NKV * HDIM];
__device__ __nv_bfloat16 g_v_hi [T_TOK * NKV * HDIM], g_v_lo [T_TOK * NKV * HDIM];
// fp16 single weights
__device__ __half g_wqkv[3072 * 2048];
__device__ __half g_wo[2048 * 2048];
__device__ __half g_wgu[NE * 2048 * D_MODEL];  // interleaved gate/up
__device__ __half g_wd[NE * D_MODEL * NF];

// ---------------- PTX helpers ----------------
__device__ __forceinline__ uint32_t smem_u32(const void* p) {
    return (uint32_t)__cvta_generic_to_shared(p);
}
__device__ __forceinline__ void cpa16(uint32_t dst, const void* src) {
    asm volatile("cp.async.cg.shared.global [%0], [%1], 16;" :: "r"(dst), "l"(src));
}
__device__ __forceinline__ void cp_commit() { asm volatile("cp.async.commit_group;" ::: "memory"); }
__device__ __forceinline__ void cp_wait1()  { asm volatile("cp.async.wait_group 1;" ::: "memory"); }
__device__ __forceinline__ void cp_wait0()  { asm volatile("cp.async.wait_group 0;" ::: "memory"); }

__device__ __forceinline__ void ldsm_x4(uint32_t r[4], uint32_t addr) {
    asm volatile("ldmatrix.sync.aligned.m8n8.x4.shared.b16 {%0,%1,%2,%3}, [%4];"
                 : "=r"(r[0]), "=r"(r[1]), "=r"(r[2]), "=r"(r[3]) : "r"(addr));
}
__device__ __forceinline__ void ldsm_x4_t(uint32_t r[4], uint32_t addr) {
    asm volatile("ldmatrix.sync.aligned.m8n8.x4.trans.shared.b16 {%0,%1,%2,%3}, [%4];"
                 : "=r"(r[0]), "=r"(r[1]), "=r"(r[2]), "=r"(r[3]) : "r"(addr));
}
// bf16 mma (attention)
__device__ __forceinline__ void mma_16816(float acc[4], const uint32_t a[4], const uint32_t b[2]) {
    asm volatile(
        "mma.sync.aligned.m16n8k16.row.col.f32.bf16.bf16.f32 "
        "{%0,%1,%2,%3}, {%4,%5,%6,%7}, {%8,%9}, {%0,%1,%2,%3};"
        : "+f"(acc[0]), "+f"(acc[1]), "+f"(acc[2]), "+f"(acc[3])
        : "r"(a[0]), "r"(a[1]), "r"(a[2]), "r"(a[3]), "r"(b[0]), "r"(b[1]));
}
// fp16 mma (GEMMs)
__device__ __forceinline__ void mma_16816h(float acc[4], const uint32_t a[4], const uint32_t b[2]) {
    asm volatile(
        "mma.sync.aligned.m16n8k16.row.col.f32.f16.f16.f32 "
        "{%0,%1,%2,%3}, {%4,%5,%6,%7}, {%8,%9}, {%0,%1,%2,%3};"
        : "+f"(acc[0]), "+f"(acc[1]), "+f"(acc[2]), "+f"(acc[3])
        : "r"(a[0]), "r"(a[1]), "r"(a[2]), "r"(a[3]), "r"(b[0]), "r"(b[1]));
}
__device__ __forceinline__ void split_store_bf(float v, __nv_bfloat16* hp, __nv_bfloat16* lp) {
    __nv_bfloat16 h = __float2bfloat16_rn(v);
    *hp = h;
    *lp = __float2bfloat16_rn(v - __bfloat162float(h));
}
__device__ __forceinline__ void split_store_h(float v, __half* hp, __half* lp) {
    __half h = __float2half_rn(v);
    *hp = h;
    *lp = __float2half_rn(v - __half2float(h));
}
__device__ __forceinline__ uint32_t bf2u(__nv_bfloat162 h) {
    uint32_t u;
    asm("mov.b32 %0, {%1, %2};" : "=r"(u)
        : "h"(__bfloat16_as_ushort(h.x)), "h"(__bfloat16_as_ushort(h.y)));
    return u;
}

// ---------------- fp32 -> fp16 convert (weights, 2x ILP) ----------------
__global__ void conv_kernel(const float4* __restrict__ s, __half2* __restrict__ d, int n4) {
    int i = (blockIdx.x * blockDim.x + threadIdx.x) * 2;
    int stride = gridDim.x * blockDim.x * 2;
    for (; i < n4; i += stride) {
        float4 v0 = s[i];
        float4 v1 = s[i + 1];
        d[i * 2 + 0] = __floats2half2_rn(v0.x, v0.y);
        d[i * 2 + 1] = __floats2half2_rn(v0.z, v0.w);
        d[i * 2 + 2] = __floats2half2_rn(v1.x, v1.y);
        d[i * 2 + 3] = __floats2half2_rn(v1.z, v1.w);
    }
}

// ---------------- gate/up interleave convert: src (e,f,d) -> dst row e*2048 + 2f + sel ----
__global__ void conv_interleave(const float4* __restrict__ s, __half2* __restrict__ d, int sel) {
    int n4 = NE * NF * (D_MODEL / 4);
    int i = (blockIdx.x * blockDim.x + threadIdx.x) * 2;
    int stride = gridDim.x * blockDim.x * 2;
    for (; i < n4; i += stride) {
        float4 v0 = s[i];
        float4 v1 = s[i + 1];
#pragma unroll
        for (int j = 0; j < 2; j++) {
            float4 v = j ? v1 : v0;
            int k = i + j;
            int d4 = k & 511;
            int fidx = k >> 9;
            int f = fidx & (NF - 1);
            int e = fidx >> 10;
            size_t dst2 = (size_t)(e * 2048 + 2 * f + sel) * 512 + d4;
            d[dst2 * 2 + 0] = __floats2half2_rn(v.x, v.y);
            d[dst2 * 2 + 1] = __floats2half2_rn(v.z, v.w);
        }
    }
}

// ---------------- rmsnorm + fp16 split (optionally zeroes expert counters) ----------------
__global__ void rmsnorm_split(const float* __restrict__ x, const float* __restrict__ w,
                              float* __restrict__ outf, __half* __restrict__ hi,
                              __half* __restrict__ lo, int zflag) {
    int row = blockIdx.x;
    int tid = threadIdx.x;  // 256
    if (zflag && row == 0 && tid < NE) g_expcnt[tid] = 0;
    const float* xr = x + (size_t)row * D_MODEL;
    float xv[8];
    float ss = 0.f;
#pragma unroll
    for (int i = 0; i < 8; i++) {
        xv[i] = xr[tid + i * 256];
        ss += xv[i] * xv[i];
    }
#pragma unroll
    for (int o = 16; o > 0; o >>= 1) ss += __shfl_xor_sync(0xffffffffu, ss, o);
    __shared__ float sred[8];
    if ((tid & 31) == 0) sred[tid >> 5] = ss;
    __syncthreads();
    float tot = 0.f;
#pragma unroll
    for (int i = 0; i < 8; i++) tot += sred[i];
    float rs = rsqrtf(tot / (float)D_MODEL + 1e-6f);
    size_t base = (size_t)row * D_MODEL;
#pragma unroll
    for (int i = 0; i < 8; i++) {
        int d = tid + i * 256;
        float v = xv[i] * rs * w[d];
        if (outf) outf[base + d] = v;
        split_store_h(v, hi + base + d, lo + base + d);
    }
}

// ---------------- per-head rmsnorm + RoPE: one WARP per head ----------------
// hi==null: write fp32 in place (Q); else bf16 split (K, for attention).
__global__ void qknorm_rope(float* __restrict__ data, const float* __restrict__ w, int nheads,
                            __nv_bfloat16* __restrict__ hi, __nv_bfloat16* __restrict__ lo) {
    int gw = blockIdx.x * 8 + (threadIdx.x >> 5);
    int lane = threadIdx.x & 31;
    int t = gw / nheads;
    int h = gw - t * nheads;
    size_t off = ((size_t)t * nheads + h) * HDIM + lane * 4;
    float4 v = *(float4*)&data[off];
    float ss = v.x * v.x + v.y * v.y + v.z * v.z + v.w * v.w;
#pragma unroll
    for (int o = 16; o > 0; o >>= 1) ss += __shfl_xor_sync(0xffffffffu, ss, o);
    float rs = rsqrtf(ss * (1.f / 128.f) + 1e-6f);
    const float4 wv = *(const float4*)&w[lane * 4];
    v.x *= rs * wv.x; v.y *= rs * wv.y; v.z *= rs * wv.z; v.w *= rs * wv.w;
    float4 p;
    p.x = __shfl_xor_sync(0xffffffffu, v.x, 16);
    p.y = __shfl_xor_sync(0xffffffffu, v.y, 16);
    p.z = __shfl_xor_sync(0xffffffffu, v.z, 16);
    p.w = __shfl_xor_sync(0xffffffffu, v.w, 16);
    int s = t & (S_SEQ - 1);
    int ibase = (lane * 4) & 63;
    bool lohalf = lane < 16;
    float o4[4];
    float vv[4] = {v.x, v.y, v.z, v.w};
    float pp[4] = {p.x, p.y, p.z, p.w};
#pragma unroll
    for (int c = 0; c < 4; c++) {
        float fi = exp2f(-(float)(ibase + c) * 0.20762050592154265f);
        float ang = (float)s * fi;
        float sn, cs;
        sincosf(ang, &sn, &cs);
        o4[c] = lohalf ? (vv[c] * cs - pp[c] * sn) : (pp[c] * sn + vv[c] * cs);
    }
    if (hi) {
#pragma unroll
        for (int c = 0; c < 4; c++) split_store_bf(o4[c], hi + off + c, lo + off + c);
    } else {
        *(float4*)&data[off] = make_float4(o4[0], o4[1], o4[2], o4[3]);
    }
}

// ---------------- HMMA causal flash attention (bf16x3, proven; O -> fp16 split) -------
#define AT_SMEM (65536 + 2 * 65536)

__device__ __forceinline__ uint32_t tile_addr(uint32_t base, int row, int chunk) {
    return base + (uint32_t)(row * 256) + (uint32_t)((chunk ^ (row & 7)) << 4);
}

__global__ __launch_bounds__(256, 1) void attn_hmma(
    const float* __restrict__ Q,
    const __nv_bfloat16* __restrict__ Kh, const __nv_bfloat16* __restrict__ Kl,
    const __nv_bfloat16* __restrict__ Vh, const __nv_bfloat16* __restrict__ Vl,
    __half* __restrict__ Ohi, __half* __restrict__ Olo) {
    extern __shared__ char dsm[];
    uint32_t sb = smem_u32(dsm);
    const uint32_t Qh_s = sb, Ql_s = sb + 32768u;
    int qb = 15 - (int)blockIdx.x;
    int h = blockIdx.y, b = blockIdx.z;
    int tid = threadIdx.x;
    int w = tid >> 5, lane = tid & 31;
    int kvh = h >> 2;
    int qg = lane >> 3, sub = lane & 7;
    int qr = lane >> 2, qc2 = (lane & 3) * 2;
    const float e2 = 0.12751743f;  // log2(e)/sqrt(128)

#pragma unroll
    for (int i = 0; i < 16; i++) {
        int idx = i * 256 + tid;
        int row = idx >> 5;
        int d4 = (idx & 31) * 4;
        const float4 v = *(const float4*)&Q[(((size_t)(b * S_SEQ + qb * 128 + row) * NH + h) << 7) + d4];
        __nv_bfloat162 h0 = __floats2bfloat162_rn(v.x, v.y);
        __nv_bfloat162 h1 = __floats2bfloat162_rn(v.z, v.w);
        __nv_bfloat162 l0v = __floats2bfloat162_rn(v.x - __bfloat162float(h0.x),
                                                   v.y - __bfloat162float(h0.y));
        __nv_bfloat162 l1v = __floats2bfloat162_rn(v.z - __bfloat162float(h1.x),
                                                   v.w - __bfloat162float(h1.y));
        uint32_t a = (uint32_t)(row * 256 + (((d4 >> 3) ^ (row & 7)) << 4) + (d4 & 7) * 2);
        *(__nv_bfloat162*)(dsm + a) = h0;
        *(__nv_bfloat162*)(dsm + a + 4) = h1;
        *(__nv_bfloat162*)(dsm + 32768 + a) = l0v;
        *(__nv_bfloat162*)(dsm + 32768 + a + 4) = l1v;
    }

    auto prefetch = [&](int kb, int buf) {
        uint32_t base = sb + 65536u + (uint32_t)buf * 65536u;
#pragma unroll
        for (int i = 0; i < 16; i++) {
            int ci = i * 256 + tid;
            int mat = ci >> 10;
            int idx = ci & 1023;
            int row = idx >> 4, chunk = idx & 15;
            uint32_t dst = tile_addr(base + (uint32_t)mat * 16384u, row, chunk);
            size_t goff = (((size_t)(b * S_SEQ + kb * 64 + row) * NKV + kvh) << 7) + chunk * 8;
            const __nv_bfloat16* src;
            if (mat == 0) src = Kh + goff;
            else if (mat == 1) src = Kl + goff;
            else if (mat == 2) src = Vh + goff;
            else src = Vl + goff;
            cpa16(dst, src);
        }
        cp_commit();
    };

    float Oa[16][4];
#pragma unroll
    for (int d = 0; d < 16; d++)
#pragma unroll
        for (int j = 0; j < 4; j++) Oa[d][j] = 0.f;
    float m0 = -1e30f, m1 = -1e30f, l0 = 0.f, l1 = 0.f;

    int nkb = 2 * qb + 2;
    prefetch(0, 0);

    for (int kb = 0; kb < nkb; kb++) {
        cp_wait0();
        __syncthreads();
        if (kb + 1 < nkb) prefetch(kb + 1, (kb + 1) & 1);
        uint32_t kv = sb + 65536u + (uint32_t)(kb & 1) * 65536u;
        uint32_t Kh_t = kv, Kl_t = kv + 16384u, Vh_t = kv + 32768u, Vl_t = kv + 49152u;

        float s[8][4];
#pragma unroll
        for (int nb = 0; nb < 8; nb++)
#pragma unroll
            for (int j = 0; j < 4; j++) s[nb][j] = 0.f;

#pragma unroll
        for (int kc = 0; kc < 8; kc++) {
            uint32_t ah[4], al[4];
            int arow = w * 16 + (qg & 1) * 8 + sub;
            int achk = kc * 2 + (qg >> 1);
            ldsm_x4(ah, tile_addr(Qh_s, arow, achk));
            ldsm_x4(al, tile_addr(Ql_s, arow, achk));
#pragma unroll
            for (int nbp = 0; nbp < 4; nbp++) {
                uint32_t bh[4], bl[4];
                int brow = nbp * 16 + (qg >> 1) * 8 + sub;
                int bchk = kc * 2 + (qg & 1);
                ldsm_x4(bh, tile_addr(Kh_t, brow, bchk));
                ldsm_x4(bl, tile_addr(Kl_t, brow, bchk));
                mma_16816(s[2 * nbp + 0], ah, bh + 0);
                mma_16816(s[2 * nbp + 0], ah, bl + 0);
                mma_16816(s[2 * nbp + 0], al, bh + 0);
                mma_16816(s[2 * nbp + 1], ah, bh + 2);
                mma_16816(s[2 * nbp + 1], ah, bl + 2);
                mma_16816(s[2 * nbp + 1], al, bh + 2);
            }
        }

        int row0 = qb * 128 + w * 16 + qr;
        int row1 = row0 + 8;
        if (kb >= 2 * qb) {
            int colb = kb * 64 + qc2;
#pragma unroll
            for (int nb = 0; nb < 8; nb++) {
                int c0 = colb + nb * 8, c1 = c0 + 1;
                if (c0 > row0) s[nb][0] = -1e30f;
                if (c1 > row0) s[nb][1] = -1e30f;
                if (c0 > row1) s[nb][2] = -1e30f;
                if (c1 > row1) s[nb][3] = -1e30f;
            }
        }
        float mx0 = -1e30f, mx1 = -1e30f;
#pragma unroll
        for (int nb = 0; nb < 8; nb++) {
            mx0 = fmaxf(mx0, fmaxf(s[nb][0], s[nb][1]));
            mx1 = fmaxf(mx1, fmaxf(s[nb][2], s[nb][3]));
        }
        mx0 = fmaxf(mx0, __shfl_xor_sync(0xffffffffu, mx0, 1));
        mx0 = fmaxf(mx0, __shfl_xor_sync(0xffffffffu, mx0, 2));
        mx1 = fmaxf(mx1, __shfl_xor_sync(0xffffffffu, mx1, 1));
        mx1 = fmaxf(mx1, __shfl_xor_sync(0xffffffffu, mx1, 2));
        float mn0 = fmaxf(m0, mx0), mn1 = fmaxf(m1, mx1);
        float f0 = exp2f((m0 - mn0) * e2), f1 = exp2f((m1 - mn1) * e2);
        m0 = mn0; m1 = mn1;
        l0 *= f0; l1 *= f1;
#pragma unroll
        for (int d = 0; d < 16; d++) {
            Oa[d][0] *= f0; Oa[d][1] *= f0;
            Oa[d][2] *= f1; Oa[d][3] *= f1;
        }
#pragma unroll
        for (int nb = 0; nb < 8; nb++) {
            s[nb][0] = exp2f((s[nb][0] - mn0) * e2);
            s[nb][1] = exp2f((s[nb][1] - mn0) * e2);
            s[nb][2] = exp2f((s[nb][2] - mn1) * e2);
            s[nb][3] = exp2f((s[nb][3] - mn1) * e2);
            l0 += s[nb][0] + s[nb][1];
            l1 += s[nb][2] + s[nb][3];
        }

#pragma unroll
        for (int kk = 0; kk < 4; kk++) {
            uint32_t ph[4], pl[4];
            float* p0 = s[2 * kk];
            float* p1 = s[2 * kk + 1];
            __nv_bfloat162 h00 = __floats2bfloat162_rn(p0[0], p0[1]);
            __nv_bfloat162 h01 = __floats2bfloat162_rn(p0[2], p0[3]);
            __nv_bfloat162 h10 = __floats2bfloat162_rn(p1[0], p1[1]);
            __nv_bfloat162 h11 = __floats2bfloat162_rn(p1[2], p1[3]);
            ph[0] = bf2u(h00); ph[1] = bf2u(h01);
            ph[2] = bf2u(h10); ph[3] = bf2u(h11);
            pl[0] = bf2u(__floats2bfloat162_rn(p0[0] - __bfloat162float(h00.x),
                                               p0[1] - __bfloat162float(h00.y)));
            pl[1] = bf2u(__floats2bfloat162_rn(p0[2] - __bfloat162float(h01.x),
                                               p0[3] - __bfloat162float(h01.y)));
            pl[2] = bf2u(__floats2bfloat162_rn(p1[0] - __bfloat162float(h10.x),
                                               p1[1] - __bfloat162float(h10.y)));
            pl[3] = bf2u(__floats2bfloat162_rn(p1[2] - __bfloat162float(h11.x),
                                               p1[3] - __bfloat162float(h11.y)));
#pragma unroll
            for (int dbp = 0; dbp < 8; dbp++) {
                uint32_t vh[4], vl[4];
                int vrow = kk * 16 + (qg & 1) * 8 + sub;
                int vchk = dbp * 2 + (qg >> 1);
                ldsm_x4_t(vh, tile_addr(Vh_t, vrow, vchk));
                ldsm_x4_t(vl, tile_addr(Vl_t, vrow, vchk));
                mma_16816(Oa[2 * dbp + 0], ph, vh + 0);
                mma_16816(Oa[2 * dbp + 0], ph, vl + 0);
                mma_16816(Oa[2 * dbp + 0], pl, vh + 0);
                mma_16816(Oa[2 * dbp + 1], ph, vh + 2);
                mma_16816(Oa[2 * dbp + 1], ph, vl + 2);
                mma_16816(Oa[2 * dbp + 1], pl, vh + 2);
            }
        }
    }

    l0 += __shfl_xor_sync(0xffffffffu, l0, 1);
    l0 += __shfl_xor_sync(0xffffffffu, l0, 2);
    l1 += __shfl_xor_sync(0xffffffffu, l1, 1);
    l1 += __shfl_xor_sync(0xffffffffu, l1, 2);
    float i0 = 1.f / l0, i1 = 1.f / l1;
    int row0 = qb * 128 + w * 16 + qr;
#pragma unroll
    for (int db = 0; db < 16; db++) {
        int col = h * 128 + db * 8 + qc2;
        size_t a0 = ((size_t)(b * S_SEQ + row0) << 11) + col;
        size_t a1 = ((size_t)(b * S_SEQ + row0 + 8) << 11) + col;
        float v0 = Oa[db][0] * i0, v1 = Oa[db][1] * i0;
        float v2 = Oa[db][2] * i1, v3 = Oa[db][3] * i1;
        __half2 h0 = __floats2half2_rn(v0, v1);
        __half2 h1 = __floats2half2_rn(v2, v3);
        *(__half2*)&Ohi[a0] = h0;
        *(__half2*)&Ohi[a1] = h1;
        *(__half2*)&Olo[a0] = __floats2half2_rn(v0 - __half2float(h0.x),
                                                v1 - __half2float(h0.y));
        *(__half2*)&Olo[a1] = __floats2half2_rn(v2 - __half2float(h1.x),
                                                v3 - __half2float(h1.y));
    }
}

// ---------------- router ----------------
__global__ void router_kernel(const float* __restrict__ h2, const float* __restrict__ wr) {
    int t = blockIdx.x;
    int tid = threadIdx.x;  // 256
    float p[8];
#pragma unroll
    for (int e = 0; e < 8; e++) p[e] = 0.f;
#pragma unroll
    for (int i = 0; i < 8; i++) {
        int d = tid + i * 256;
        float hv = h2[(size_t)t * D_MODEL + d];
#pragma unroll
        for (int e = 0; e < 8; e++) p[e] += hv * wr[e * D_MODEL + d];
    }
    __shared__ float red[8][256];
#pragma unroll
    for (int e = 0; e < 8; e++) red[e][tid] = p[e];
    __syncthreads();
    for (int stp = 128; stp > 0; stp >>= 1) {
        if (tid < stp) {
#pragma unroll
            for (int e = 0; e < 8; e++) red[e][tid] += red[e][tid + stp];
        }
        __syncthreads();
    }
    if (tid == 0) {
        float lg[8];
        float m = -1e30f;
#pragma unroll
        for (int e = 0; e < 8; e++) { lg[e] = red[e][0]; m = fmaxf(m, lg[e]); }
        float pr[8];
#pragma unroll
        for (int e = 0; e < 8; e++) pr[e] = __expf(lg[e] - m);
        int i1 = 0;
#pragma unroll
        for (int e = 1; e < 8; e++) if (pr[e] > pr[i1]) i1 = e;
        int i2 = (i1 == 0) ? 1 : 0;
#pragma unroll
        for (int e = 0; e < 8; e++) if (e != i1 && pr[e] > pr[i2]) i2 = e;
        float v1 = pr[i1], v2 = pr[i2];
        float denom = v1 + v2;
        int pos1 = atomicAdd(&g_expcnt[i1], 1);
        g_toklist[i1 * LIST_STRIDE + pos1] = t * 2;
        g_entrygate[t * 2] = v1 / denom;
        int pos2 = atomicAdd(&g_expcnt[i2], 1);
        g_toklist[i2 * LIST_STRIDE + pos2] = t * 2 + 1;
        g_entrygate[t * 2 + 1] = v2 / denom;
    }
}

// ---------------- fp16 2-term HMMA GEMM: C[M,N] = (Ah+Al) @ B^T ----------------
// CTA tile 128x128, BK=32, 8 warps (2x4), warp tile 64x32, 3-stage, single sync.
// Stage: Ah 8K | Al 8K | B 8K (24KB). Terms: Ah*B + Al*B.
// modes: 0 dense fp32 (+resid), 2 MoE-down atomic, 4 MoE gate/up interleaved + silu,
// 6 fused QKV epilogue (Q fp32 / K fp32 / V bf16 split).
#define STAGE_BYTES 24576
#define HM_SMEM (3 * STAGE_BYTES)

__device__ __forceinline__ uint32_t sw_addr(uint32_t base, int row, int kchunk) {
    return base + (uint32_t)(row * 64) + (uint32_t)((kchunk ^ ((row >> 1) & 3)) << 4);
}

__global__ __launch_bounds__(256) void hmma_gemm(
    const __half* __restrict__ Ahi, const __half* __restrict__ Alo,
    const __half* __restrict__ B,
    float* __restrict__ C, int N, int K,
    const float* __restrict__ resid, int mode) {
    extern __shared__ char dsm[];
    __shared__ int arowS[128];
    __shared__ int crowS[128];

    int tid = threadIdx.x;
    int n0 = blockIdx.x * 128;
    int mb = blockIdx.y * 128;
    int e = blockIdx.z;
    int cnt = 1 << 30;
    bool moe = (mode == 2 || mode == 4);
    if (moe) {
        cnt = g_expcnt[e];
        if (mb >= cnt) return;
        B += (size_t)e * N * K;
    }
    if (tid < 128) {
        if (moe) {
            int idx = mb + tid;
            if (idx > cnt - 1) idx = cnt - 1;
            int entry = g_toklist[e * LIST_STRIDE + idx];
            crowS[tid] = entry;
            arowS[tid] = (mode == 4) ? (entry >> 1) : entry;
        } else {
            arowS[tid] = mb + tid;
            crowS[tid] = mb + tid;
        }
    }
    __syncthreads();

    uint32_t sb = smem_u32(dsm);

    auto load_tile = [&](int stage, int k0) {
        uint32_t sbase = sb + (uint32_t)stage * STAGE_BYTES;
#pragma unroll
        for (int i = 0; i < 6; i++) {
            int ci = i * 256 + tid;  // 0..1535
            int mat = ci >> 9;       // 0=Ah 1=Al 2=B
            int idx = ci & 511;
            int r = idx >> 2, c = idx & 3;
            uint32_t dst = sw_addr(sbase + (uint32_t)mat * 8192u, r, c);
            const __half* src;
            if (mat == 0) src = Ahi + (size_t)arowS[r] * K + k0 + c * 8;
            else if (mat == 1) src = Alo + (size_t)arowS[r] * K + k0 + c * 8;
            else src = B + (size_t)(n0 + r) * K + k0 + c * 8;
            cpa16(dst, src);
        }
        cp_commit();
    };

    int T = K >> 5;
    load_tile(0, 0);
    load_tile(1, 32);

    int warp = tid >> 5, lane = tid & 31;
    int wm = warp >> 2, wn = warp & 3;
    int q = lane >> 3, sub = lane & 7;

    float acc[4][4][4];
#pragma unroll
    for (int mi = 0; mi < 4; mi++)
#pragma unroll
        for (int nj = 0; nj < 4; nj++)
#pragma unroll
            for (int v = 0; v < 4; v++) acc[mi][nj][v] = 0.f;

    for (int kt = 0; kt < T; kt++) {
        if (kt < T - 1) cp_wait1(); else cp_wait0();
        __syncthreads();
        if (kt + 2 < T) load_tile((kt + 2) % 3, (kt + 2) * 32);
        uint32_t sbase = sb + (uint32_t)(kt % 3) * STAGE_BYTES;
        uint32_t aH = sbase, aL = sbase + 8192u, bB = sbase + 16384u;
#pragma unroll
        for (int ks = 0; ks < 2; ks++) {
            uint32_t ah[4][4], al[4][4], bb[2][4];
#pragma unroll
            for (int mi = 0; mi < 4; mi++) {
                int row = wm * 64 + mi * 16 + (q & 1) * 8 + sub;
                int kc = ks * 2 + (q >> 1);
                ldsm_x4(ah[mi], sw_addr(aH, row, kc));
                ldsm_x4(al[mi], sw_addr(aL, row, kc));
            }
#pragma unroll
            for (int gj = 0; gj < 2; gj++) {
                int row = wn * 32 + gj * 16 + (q >> 1) * 8 + sub;
                int kc = ks * 2 + (q & 1);
                ldsm_x4(bb[gj], sw_addr(bB, row, kc));
            }
#pragma unroll
            for (int mi = 0; mi < 4; mi++)
#pragma unroll
                for (int nj = 0; nj < 4; nj++) {
                    const uint32_t* pb = &bb[nj >> 1][(nj & 1) * 2];
                    mma_16816h(acc[mi][nj], ah[mi], pb);
                    mma_16816h(acc[mi][nj], al[mi], pb);
                }
        }
    }

    int qr = lane >> 2, qc = lane & 3;
#pragma unroll
    for (int mi = 0; mi < 4; mi++) {
#pragma unroll
        for (int half = 0; half < 2; half++) {
            int rl = wm * 64 + mi * 16 + half * 8 + qr;
            if (moe && mb + rl >= cnt) continue;
            if (mode == 6) {
                int grow = mb + rl;
#pragma unroll
                for (int nj = 0; nj < 4; nj++) {
                    float v0 = acc[mi][nj][half * 2 + 0];
                    float v1 = acc[mi][nj][half * 2 + 1];
                    int col = n0 + wn * 32 + qc * 2 + nj * 8;
                    if (n0 < 2048) {
                        *(float2*)&C[(size_t)grow * 2048 + col] = make_float2(v0, v1);
                    } else if (n0 < 2560) {
                        *(float2*)&g_k[(size_t)grow * 512 + col - 2048] = make_float2(v0, v1);
                    } else {
                        size_t a = (size_t)grow * 512 + col - 2560;
                        __nv_bfloat162 hv = __floats2bfloat162_rn(v0, v1);
                        *(__nv_bfloat162*)&g_v_hi[a] = hv;
                        *(__nv_bfloat162*)&g_v_lo[a] =
                            __floats2bfloat162_rn(v0 - __bfloat162float(hv.x),
                                                  v1 - __bfloat162float(hv.y));
                    }
                }
            } else if (mode == 4) {
                int entry = crowS[rl];
                float eg = g_entrygate[entry];
#pragma unroll
                for (int nj = 0; nj < 4; nj++) {
                    float gv = acc[mi][nj][half * 2 + 0];
                    float uv = acc[mi][nj][half * 2 + 1];
                    int f = (n0 + wn * 32 + qc * 2 + nj * 8) >> 1;
                    float a = eg * (gv / (1.f + __expf(-gv))) * uv;
                    size_t ai = (size_t)entry * NF + f;
                    split_store_h(a, g_act_hi + ai, g_act_lo + ai);
                }
            } else if (mode == 2) {
                size_t gbase = (size_t)(crowS[rl] >> 1) * N + n0 + wn * 32 + qc * 2;
#pragma unroll
                for (int nj = 0; nj < 4; nj++) {
                    atomicAdd(&C[gbase + nj * 8 + 0], acc[mi][nj][half * 2 + 0]);
                    atomicAdd(&C[gbase + nj * 8 + 1], acc[mi][nj][half * 2 + 1]);
                }
            } else {  // mode 0
                size_t gbase = (size_t)(mb + rl) * N + n0 + wn * 32 + qc * 2;
#pragma unroll
                for (int nj = 0; nj < 4; nj++) {
                    float v0 = acc[mi][nj][half * 2 + 0];
                    float v1 = acc[mi][nj][half * 2 + 1];
                    size_t addr = gbase + nj * 8;
                    if (resid) {
                        v0 += resid[addr + 0];
                        v1 += resid[addr + 1];
                    }
                    *(float2*)&C[addr] = make_float2(v0, v1);
                }
            }
        }
    }
}

// ---------------- host launch ----------------
extern "C" void kernel_launch(void* const* d_in, const int* in_sizes, int n_in,
                              void* d_out, int out_size) {
    const float* x          = (const float*)d_in[0];
    const float* wattn_norm = (const float*)d_in[1];
    const float* wq         = (const float*)d_in[2];
    const float* wk         = (const float*)d_in[3];
    const float* wv         = (const float*)d_in[4];
    const float* wq_norm    = (const float*)d_in[5];
    const float* wk_norm    = (const float*)d_in[6];
    const float* wattn_out  = (const float*)d_in[7];
    const float* wffn_norm  = (const float*)d_in[8];
    const float* w_router   = (const float*)d_in[9];
    const float* w_gate     = (const float*)d_in[10];
    const float* w_up       = (const float*)d_in[11];
    const float* w_down     = (const float*)d_in[12];
    float* out = (float*)d_out;

    cudaFuncSetAttribute(hmma_gemm, cudaFuncAttributeMaxDynamicSharedMemorySize, HM_SMEM);
    cudaFuncSetAttribute(attn_hmma, cudaFuncAttributeMaxDynamicSharedMemorySize, AT_SMEM);

    float *p_q, *p_k, *p_h2;
    cudaGetSymbolAddress((void**)&p_q, g_q);
    cudaGetSymbolAddress((void**)&p_k, g_k);
    cudaGetSymbolAddress((void**)&p_h2, g_h2);

    __half *hh, *hl, *h2h, *h2l, *oh, *ol, *ah, *al;
    __half *wqkv_, *wo_, *wgu_, *wd_;
    __nv_bfloat16 *kh_, *kl_, *vh_, *vl_;
    cudaGetSymbolAddress((void**)&hh, g_h_hi);   cudaGetSymbolAddress((void**)&hl, g_h_lo);
    cudaGetSymbolAddress((void**)&h2h, g_h2_hi); cudaGetSymbolAddress((void**)&h2l, g_h2_lo);
    cudaGetSymbolAddress((void**)&oh, g_o_hi);   cudaGetSymbolAddress((void**)&ol, g_o_lo);
    cudaGetSymbolAddress((void**)&ah, g_act_hi); cudaGetSymbolAddress((void**)&al, g_act_lo);
    cudaGetSymbolAddress((void**)&kh_, g_k_hi);  cudaGetSymbolAddress((void**)&kl_, g_k_lo);
    cudaGetSymbolAddress((void**)&vh_, g_v_hi);  cudaGetSymbolAddress((void**)&vl_, g_v_lo);
    cudaGetSymbolAddress((void**)&wqkv_, g_wqkv);
    cudaGetSymbolAddress((void**)&wo_, g_wo);
    cudaGetSymbolAddress((void**)&wgu_, g_wgu);
    cudaGetSymbolAddress((void**)&wd_, g_wd);

    // weight conversions (fp32 -> fp16 single)
    conv_kernel<<<512, 256>>>((const float4*)wq, (__half2*)wqkv_, 2048 * 512);
    conv_kernel<<<128, 256>>>((const float4*)wk, (__half2*)(wqkv_ + 2048 * 2048), 512 * 512);
    conv_kernel<<<128, 256>>>((const float4*)wv, (__half2*)(wqkv_ + 2560 * 2048), 512 * 512);
    // h = rmsnorm(x) -> fp16 split
    rmsnorm_split<<<T_TOK, 256>>>(x, wattn_norm, nullptr, hh, hl, 0);
    conv_kernel<<<512, 256>>>((const float4*)wattn_out, (__half2*)wo_, 2048 * 512);
    // fused QKV projection (fp16 2-term)
    hmma_gemm<<<dim3(24, 32, 1), 256, HM_SMEM>>>(hh, hl, wqkv_, p_q, 3072, 2048, nullptr, 6);
    // qk norm + rope
    qknorm_rope<<<T_TOK * NH / 8, 256>>>(p_q, wq_norm, NH, nullptr, nullptr);
    qknorm_rope<<<T_TOK * NKV / 8, 256>>>(p_k, wk_norm, NKV, kh_, kl_);
    // flash attention (bf16x3) -> O fp16 split
    attn_hmma<<<dim3(16, NH, 2), 256, AT_SMEM>>>(p_q, kh_, kl_, vh_, vl_, oh, ol);
    // out projection + residual -> d_out
    hmma_gemm<<<dim3(16, 32, 1), 256, HM_SMEM>>>(oh, ol, wo_, out, 2048, 2048, x, 0);
    // h2 = rmsnorm(out) (+ zero expert counters)
    rmsnorm_split<<<T_TOK, 256>>>(out, wffn_norm, p_h2, h2h, h2l, 1);
    // router
    router_kernel<<<T_TOK, 256>>>(p_h2, w_router);
    // MoE weight conversions
    conv_interleave<<<1024, 256>>>((const float4*)w_gate, (__half2*)wgu_, 0);
    conv_interleave<<<1024, 256>>>((const float4*)w_up, (__half2*)wgu_, 1);
    conv_kernel<<<1024, 256>>>((const float4*)w_down, (__half2*)wd_, NE * D_MODEL * 256);
    // fused gate/up GEMM + silu + router gate -> act fp16 split
    hmma_gemm<<<dim3(16, 64, NE), 256, HM_SMEM>>>(h2h, h2l, wgu_, nullptr, 2048, 2048, nullptr, 4);
    // down projection, scatter-add into out
    hmma_gemm<<<dim3(16, 64, NE), 256, HM_SMEM>>>(ah, al, wd_, out, D_MODEL, NF, nullptr, 2);
}

// round 15
// speedup vs baseline: 1.4768x; 1.0901x over previous
#include <cuda_runtime.h>
#include <cuda_fp16.h>
#include <math.h>
#include <stdint.h>

#define T_TOK 4096
#define D_MODEL 2048
#define S_SEQ 2048
#define NH 16
#define NKV 4
#define HDIM 128
#define NE 8
#define NF 1024
#define LIST_STRIDE (2 * T_TOK)

// ---------------- scratch (static device allocations; no cudaMalloc) ----------------
__device__ float g_q  [T_TOK * NH * HDIM];
__device__ float g_k  [T_TOK * NKV * HDIM];
__device__ float g_h2 [T_TOK * D_MODEL];
__device__ int   g_toklist[NE * LIST_STRIDE];
__device__ float g_entrygate[2 * T_TOK];
__device__ int   g_expcnt[NE];

// fp16 activation hi/lo splits (GEMM A operands)
__device__ __half g_h_hi [T_TOK * D_MODEL],  g_h_lo [T_TOK * D_MODEL];
__device__ __half g_h2_hi[T_TOK * D_MODEL],  g_h2_lo[T_TOK * D_MODEL];
__device__ __half g_o_hi [T_TOK * D_MODEL],  g_o_lo [T_TOK * D_MODEL];
__device__ __half g_act_hi[T_TOK * 2 * NF],  g_act_lo[T_TOK * 2 * NF];
// attention operands: K single fp16, V fp16 hi/lo
__device__ __half g_k16 [T_TOK * NKV * HDIM];
__device__ __half g_v_hi [T_TOK * NKV * HDIM], g_v_lo [T_TOK * NKV * HDIM];
// fp16 single weights
__device__ __half g_wqkv[3072 * 2048];
__device__ __half g_wo[2048 * 2048];
__device__ __half g_wgu[NE * 2048 * D_MODEL];  // interleaved gate/up
__device__ __half g_wd[NE * D_MODEL * NF];

// ---------------- PTX helpers ----------------
__device__ __forceinline__ uint32_t smem_u32(const void* p) {
    return (uint32_t)__cvta_generic_to_shared(p);
}
__device__ __forceinline__ void cpa16(uint32_t dst, const void* src) {
    asm volatile("cp.async.cg.shared.global [%0], [%1], 16;" :: "r"(dst), "l"(src));
}
__device__ __forceinline__ void cp_commit() { asm volatile("cp.async.commit_group;" ::: "memory"); }
__device__ __forceinline__ void cp_wait1()  { asm volatile("cp.async.wait_group 1;" ::: "memory"); }
__device__ __forceinline__ void cp_wait0()  { asm volatile("cp.async.wait_group 0;" ::: "memory"); }

__device__ __forceinline__ void ldsm_x4(uint32_t r[4], uint32_t addr) {
    asm volatile("ldmatrix.sync.aligned.m8n8.x4.shared.b16 {%0,%1,%2,%3}, [%4];"
                 : "=r"(r[0]), "=r"(r[1]), "=r"(r[2]), "=r"(r[3]) : "r"(addr));
}
__device__ __forceinline__ void ldsm_x4_t(uint32_t r[4], uint32_t addr) {
    asm volatile("ldmatrix.sync.aligned.m8n8.x4.trans.shared.b16 {%0,%1,%2,%3}, [%4];"
                 : "=r"(r[0]), "=r"(r[1]), "=r"(r[2]), "=r"(r[3]) : "r"(addr));
}
// fp16 mma
__device__ __forceinline__ void mma_16816h(float acc[4], const uint32_t a[4], const uint32_t b[2]) {
    asm volatile(
        "mma.sync.aligned.m16n8k16.row.col.f32.f16.f16.f32 "
        "{%0,%1,%2,%3}, {%4,%5,%6,%7}, {%8,%9}, {%0,%1,%2,%3};"
        : "+f"(acc[0]), "+f"(acc[1]), "+f"(acc[2]), "+f"(acc[3])
        : "r"(a[0]), "r"(a[1]), "r"(a[2]), "r"(a[3]), "r"(b[0]), "r"(b[1]));
}
__device__ __forceinline__ void split_store_h(float v, __half* hp, __half* lp) {
    __half h = __float2half_rn(v);
    *hp = h;
    *lp = __float2half_rn(v - __half2float(h));
}
__device__ __forceinline__ uint32_t h2u(__half2 h) {
    uint32_t u;
    asm("mov.b32 %0, {%1, %2};" : "=r"(u)
        : "h"(__half_as_ushort(h.x)), "h"(__half_as_ushort(h.y)));
    return u;
}

// ---------------- fp32 -> fp16 convert (weights, 2x ILP) ----------------
__global__ void conv_kernel(const float4* __restrict__ s, __half2* __restrict__ d, int n4) {
    int i = (blockIdx.x * blockDim.x + threadIdx.x) * 2;
    int stride = gridDim.x * blockDim.x * 2;
    for (; i < n4; i += stride) {
        float4 v0 = s[i];
        float4 v1 = s[i + 1];
        d[i * 2 + 0] = __floats2half2_rn(v0.x, v0.y);
        d[i * 2 + 1] = __floats2half2_rn(v0.z, v0.w);
        d[i * 2 + 2] = __floats2half2_rn(v1.x, v1.y);
        d[i * 2 + 3] = __floats2half2_rn(v1.z, v1.w);
    }
}

// ---------------- gate/up interleave convert: src (e,f,d) -> dst row e*2048 + 2f + sel ----
__global__ void conv_interleave(const float4* __restrict__ s, __half2* __restrict__ d, int sel) {
    int n4 = NE * NF * (D_MODEL / 4);
    int i = (blockIdx.x * blockDim.x + threadIdx.x) * 2;
    int stride = gridDim.x * blockDim.x * 2;
    for (; i < n4; i += stride) {
        float4 v0 = s[i];
        float4 v1 = s[i + 1];
#pragma unroll
        for (int j = 0; j < 2; j++) {
            float4 v = j ? v1 : v0;
            int k = i + j;
            int d4 = k & 511;
            int fidx = k >> 9;
            int f = fidx & (NF - 1);
            int e = fidx >> 10;
            size_t dst2 = (size_t)(e * 2048 + 2 * f + sel) * 512 + d4;
            d[dst2 * 2 + 0] = __floats2half2_rn(v.x, v.y);
            d[dst2 * 2 + 1] = __floats2half2_rn(v.z, v.w);
        }
    }
}

// ---------------- rmsnorm + fp16 split (optionally zeroes expert counters) ----------------
__global__ void rmsnorm_split(const float* __restrict__ x, const float* __restrict__ w,
                              float* __restrict__ outf, __half* __restrict__ hi,
                              __half* __restrict__ lo, int zflag) {
    int row = blockIdx.x;
    int tid = threadIdx.x;  // 256
    if (zflag && row == 0 && tid < NE) g_expcnt[tid] = 0;
    const float* xr = x + (size_t)row * D_MODEL;
    float xv[8];
    float ss = 0.f;
#pragma unroll
    for (int i = 0; i < 8; i++) {
        xv[i] = xr[tid + i * 256];
        ss += xv[i] * xv[i];
    }
#pragma unroll
    for (int o = 16; o > 0; o >>= 1) ss += __shfl_xor_sync(0xffffffffu, ss, o);
    __shared__ float sred[8];
    if ((tid & 31) == 0) sred[tid >> 5] = ss;
    __syncthreads();
    float tot = 0.f;
#pragma unroll
    for (int i = 0; i < 8; i++) tot += sred[i];
    float rs = rsqrtf(tot / (float)D_MODEL + 1e-6f);
    size_t base = (size_t)row * D_MODEL;
#pragma unroll
    for (int i = 0; i < 8; i++) {
        int d = tid + i * 256;
        float v = xv[i] * rs * w[d];
        if (outf) outf[base + d] = v;
        split_store_h(v, hi + base + d, lo + base + d);
    }
}

// ---------------- per-head rmsnorm + RoPE: one WARP per head ----------------
// out16==null: write fp32 in place (Q); else single fp16 (K, for attention).
__global__ void qknorm_rope(float* __restrict__ data, const float* __restrict__ w, int nheads,
                            __half* __restrict__ out16) {
    int gw = blockIdx.x * 8 + (threadIdx.x >> 5);
    int lane = threadIdx.x & 31;
    int t = gw / nheads;
    int h = gw - t * nheads;
    size_t off = ((size_t)t * nheads + h) * HDIM + lane * 4;
    float4 v = *(float4*)&data[off];
    float ss = v.x * v.x + v.y * v.y + v.z * v.z + v.w * v.w;
#pragma unroll
    for (int o = 16; o > 0; o >>= 1) ss += __shfl_xor_sync(0xffffffffu, ss, o);
    float rs = rsqrtf(ss * (1.f / 128.f) + 1e-6f);
    const float4 wv = *(const float4*)&w[lane * 4];
    v.x *= rs * wv.x; v.y *= rs * wv.y; v.z *= rs * wv.z; v.w *= rs * wv.w;
    float4 p;
    p.x = __shfl_xor_sync(0xffffffffu, v.x, 16);
    p.y = __shfl_xor_sync(0xffffffffu, v.y, 16);
    p.z = __shfl_xor_sync(0xffffffffu, v.z, 16);
    p.w = __shfl_xor_sync(0xffffffffu, v.w, 16);
    int s = t & (S_SEQ - 1);
    int ibase = (lane * 4) & 63;
    bool lohalf = lane < 16;
    float o4[4];
    float vv[4] = {v.x, v.y, v.z, v.w};
    float pp[4] = {p.x, p.y, p.z, p.w};
#pragma unroll
    for (int c = 0; c < 4; c++) {
        float fi = exp2f(-(float)(ibase + c) * 0.20762050592154265f);
        float ang = (float)s * fi;
        float sn, cs;
        sincosf(ang, &sn, &cs);
        o4[c] = lohalf ? (vv[c] * cs - pp[c] * sn) : (pp[c] * sn + vv[c] * cs);
    }
    if (out16) {
        __half2 a = __floats2half2_rn(o4[0], o4[1]);
        __half2 b = __floats2half2_rn(o4[2], o4[3]);
        *(__half2*)&out16[off + 0] = a;
        *(__half2*)&out16[off + 2] = b;
    } else {
        *(float4*)&data[off] = make_float4(o4[0], o4[1], o4[2], o4[3]);
    }
}

// ---------------- fp16 2-term HMMA causal flash attention ----------------
// Q fp16 hi/lo in smem; K single fp16; V fp16 hi/lo.
// Scores: Qh*K + Ql*K.  PV: P(single fp16)*Vh + P*Vl.
#define KV_STAGE 49152
#define AT_SMEM (65536 + 2 * KV_STAGE)

__device__ __forceinline__ uint32_t tile_addr(uint32_t base, int row, int chunk) {
    return base + (uint32_t)(row * 256) + (uint32_t)((chunk ^ (row & 7)) << 4);
}

__global__ __launch_bounds__(256, 1) void attn_hmma(
    const float* __restrict__ Q,
    const __half* __restrict__ K16,
    const __half* __restrict__ Vh, const __half* __restrict__ Vl,
    __half* __restrict__ Ohi, __half* __restrict__ Olo) {
    extern __shared__ char dsm[];
    uint32_t sb = smem_u32(dsm);
    const uint32_t Qh_s = sb, Ql_s = sb + 32768u;
    int qb = 15 - (int)blockIdx.x;
    int h = blockIdx.y, b = blockIdx.z;
    int tid = threadIdx.x;
    int w = tid >> 5, lane = tid & 31;
    int kvh = h >> 2;
    int qg = lane >> 3, sub = lane & 7;
    int qr = lane >> 2, qc2 = (lane & 3) * 2;
    const float e2 = 0.12751743f;  // log2(e)/sqrt(128)

    // ---- load full Q tile [128 x 128] fp32 -> fp16 hi/lo smem ----
#pragma unroll
    for (int i = 0; i < 16; i++) {
        int idx = i * 256 + tid;
        int row = idx >> 5;
        int d4 = (idx & 31) * 4;
        const float4 v = *(const float4*)&Q[(((size_t)(b * S_SEQ + qb * 128 + row) * NH + h) << 7) + d4];
        __half2 h0 = __floats2half2_rn(v.x, v.y);
        __half2 h1 = __floats2half2_rn(v.z, v.w);
        __half2 l0v = __floats2half2_rn(v.x - __half2float(h0.x), v.y - __half2float(h0.y));
        __half2 l1v = __floats2half2_rn(v.z - __half2float(h1.x), v.w - __half2float(h1.y));
        uint32_t a = (uint32_t)(row * 256 + (((d4 >> 3) ^ (row & 7)) << 4) + (d4 & 7) * 2);
        *(__half2*)(dsm + a) = h0;
        *(__half2*)(dsm + a + 4) = h1;
        *(__half2*)(dsm + 32768 + a) = l0v;
        *(__half2*)(dsm + 32768 + a + 4) = l1v;
    }

    // ---- K/V tile prefetch: 3 mats (K, Vh, Vl) of 16KB each ----
    auto prefetch = [&](int kb, int buf) {
        uint32_t base = sb + 65536u + (uint32_t)buf * (uint32_t)KV_STAGE;
#pragma unroll
        for (int i = 0; i < 12; i++) {
            int ci = i * 256 + tid;     // 0..3071
            int mat = ci >> 10;         // 0=K 1=Vh 2=Vl
            int idx = ci & 1023;
            int row = idx >> 4, chunk = idx & 15;
            uint32_t dst = tile_addr(base + (uint32_t)mat * 16384u, row, chunk);
            size_t goff = (((size_t)(b * S_SEQ + kb * 64 + row) * NKV + kvh) << 7) + chunk * 8;
            const __half* src;
            if (mat == 0) src = K16 + goff;
            else if (mat == 1) src = Vh + goff;
            else src = Vl + goff;
            cpa16(dst, src);
        }
        cp_commit();
    };

    float Oa[16][4];
#pragma unroll
    for (int d = 0; d < 16; d++)
#pragma unroll
        for (int j = 0; j < 4; j++) Oa[d][j] = 0.f;
    float m0 = -1e30f, m1 = -1e30f, l0 = 0.f, l1 = 0.f;

    int nkb = 2 * qb + 2;
    prefetch(0, 0);

    for (int kb = 0; kb < nkb; kb++) {
        cp_wait0();
        __syncthreads();
        if (kb + 1 < nkb) prefetch(kb + 1, (kb + 1) & 1);
        uint32_t kv = sb + 65536u + (uint32_t)(kb & 1) * (uint32_t)KV_STAGE;
        uint32_t K_t = kv, Vh_t = kv + 16384u, Vl_t = kv + 32768u;

        // ---- S = Q K^T (2-term) ----
        float s[8][4];
#pragma unroll
        for (int nb = 0; nb < 8; nb++)
#pragma unroll
            for (int j = 0; j < 4; j++) s[nb][j] = 0.f;

#pragma unroll
        for (int kc = 0; kc < 8; kc++) {
            uint32_t ah[4], al[4];
            int arow = w * 16 + (qg & 1) * 8 + sub;
            int achk = kc * 2 + (qg >> 1);
            ldsm_x4(ah, tile_addr(Qh_s, arow, achk));
            ldsm_x4(al, tile_addr(Ql_s, arow, achk));
#pragma unroll
            for (int nbp = 0; nbp < 4; nbp++) {
                uint32_t bk[4];
                int brow = nbp * 16 + (qg >> 1) * 8 + sub;
                int bchk = kc * 2 + (qg & 1);
                ldsm_x4(bk, tile_addr(K_t, brow, bchk));
                mma_16816h(s[2 * nbp + 0], ah, bk + 0);
                mma_16816h(s[2 * nbp + 0], al, bk + 0);
                mma_16816h(s[2 * nbp + 1], ah, bk + 2);
                mma_16816h(s[2 * nbp + 1], al, bk + 2);
            }
        }

        // ---- mask + online softmax ----
        int row0 = qb * 128 + w * 16 + qr;
        int row1 = row0 + 8;
        if (kb >= 2 * qb) {
            int colb = kb * 64 + qc2;
#pragma unroll
            for (int nb = 0; nb < 8; nb++) {
                int c0 = colb + nb * 8, c1 = c0 + 1;
                if (c0 > row0) s[nb][0] = -1e30f;
                if (c1 > row0) s[nb][1] = -1e30f;
                if (c0 > row1) s[nb][2] = -1e30f;
                if (c1 > row1) s[nb][3] = -1e30f;
            }
        }
        float mx0 = -1e30f, mx1 = -1e30f;
#pragma unroll
        for (int nb = 0; nb < 8; nb++) {
            mx0 = fmaxf(mx0, fmaxf(s[nb][0], s[nb][1]));
            mx1 = fmaxf(mx1, fmaxf(s[nb][2], s[nb][3]));
        }
        mx0 = fmaxf(mx0, __shfl_xor_sync(0xffffffffu, mx0, 1));
        mx0 = fmaxf(mx0, __shfl_xor_sync(0xffffffffu, mx0, 2));
        mx1 = fmaxf(mx1, __shfl_xor_sync(0xffffffffu, mx1, 1));
        mx1 = fmaxf(mx1, __shfl_xor_sync(0xffffffffu, mx1, 2));
        float mn0 = fmaxf(m0, mx0), mn1 = fmaxf(m1, mx1);
        float f0 = exp2f((m0 - mn0) * e2), f1 = exp2f((m1 - mn1) * e2);
        m0 = mn0; m1 = mn1;
        l0 *= f0; l1 *= f1;
#pragma unroll
        for (int d = 0; d < 16; d++) {
            Oa[d][0] *= f0; Oa[d][1] *= f0;
            Oa[d][2] *= f1; Oa[d][3] *= f1;
        }
#pragma unroll
        for (int nb = 0; nb < 8; nb++) {
            s[nb][0] = exp2f((s[nb][0] - mn0) * e2);
            s[nb][1] = exp2f((s[nb][1] - mn0) * e2);
            s[nb][2] = exp2f((s[nb][2] - mn1) * e2);
            s[nb][3] = exp2f((s[nb][3] - mn1) * e2);
            l0 += s[nb][0] + s[nb][1];
            l1 += s[nb][2] + s[nb][3];
        }

        // ---- O += P V (P single fp16, V hi/lo 2-term) ----
#pragma unroll
        for (int kk = 0; kk < 4; kk++) {
            uint32_t ph[4];
            float* p0 = s[2 * kk];
            float* p1 = s[2 * kk + 1];
            ph[0] = h2u(__floats2half2_rn(p0[0], p0[1]));
            ph[1] = h2u(__floats2half2_rn(p0[2], p0[3]));
            ph[2] = h2u(__floats2half2_rn(p1[0], p1[1]));
            ph[3] = h2u(__floats2half2_rn(p1[2], p1[3]));
#pragma unroll
            for (int dbp = 0; dbp < 8; dbp++) {
                uint32_t vh[4], vl[4];
                int vrow = kk * 16 + (qg & 1) * 8 + sub;
                int vchk = dbp * 2 + (qg >> 1);
                ldsm_x4_t(vh, tile_addr(Vh_t, vrow, vchk));
                ldsm_x4_t(vl, tile_addr(Vl_t, vrow, vchk));
                mma_16816h(Oa[2 * dbp + 0], ph, vh + 0);
                mma_16816h(Oa[2 * dbp + 0], ph, vl + 0);
                mma_16816h(Oa[2 * dbp + 1], ph, vh + 2);
                mma_16816h(Oa[2 * dbp + 1], ph, vl + 2);
            }
        }
    }

    l0 += __shfl_xor_sync(0xffffffffu, l0, 1);
    l0 += __shfl_xor_sync(0xffffffffu, l0, 2);
    l1 += __shfl_xor_sync(0xffffffffu, l1, 1);
    l1 += __shfl_xor_sync(0xffffffffu, l1, 2);
    float i0 = 1.f / l0, i1 = 1.f / l1;
    int row0 = qb * 128 + w * 16 + qr;
#pragma unroll
    for (int db = 0; db < 16; db++) {
        int col = h * 128 + db * 8 + qc2;
        size_t a0 = ((size_t)(b * S_SEQ + row0) << 11) + col;
        size_t a1 = ((size_t)(b * S_SEQ + row0 + 8) << 11) + col;
        float v0 = Oa[db][0] * i0, v1 = Oa[db][1] * i0;
        float v2 = Oa[db][2] * i1, v3 = Oa[db][3] * i1;
        __half2 h0 = __floats2half2_rn(v0, v1);
        __half2 h1 = __floats2half2_rn(v2, v3);
        *(__half2*)&Ohi[a0] = h0;
        *(__half2*)&Ohi[a1] = h1;
        *(__half2*)&Olo[a0] = __floats2half2_rn(v0 - __half2float(h0.x),
                                                v1 - __half2float(h0.y));
        *(__half2*)&Olo[a1] = __floats2half2_rn(v2 - __half2float(h1.x),
                                                v3 - __half2float(h1.y));
    }
}

// ---------------- router ----------------
__global__ void router_kernel(const float* __restrict__ h2, const float* __restrict__ wr) {
    int t = blockIdx.x;
    int tid = threadIdx.x;  // 256
    float p[8];
#pragma unroll
    for (int e = 0; e < 8; e++) p[e] = 0.f;
#pragma unroll
    for (int i = 0; i < 8; i++) {
        int d = tid + i * 256;
        float hv = h2[(size_t)t * D_MODEL + d];
#pragma unroll
        for (int e = 0; e < 8; e++) p[e] += hv * wr[e * D_MODEL + d];
    }
    __shared__ float red[8][256];
#pragma unroll
    for (int e = 0; e < 8; e++) red[e][tid] = p[e];
    __syncthreads();
    for (int stp = 128; stp > 0; stp >>= 1) {
        if (tid < stp) {
#pragma unroll
            for (int e = 0; e < 8; e++) red[e][tid] += red[e][tid + stp];
        }
        __syncthreads();
    }
    if (tid == 0) {
        float lg[8];
        float m = -1e30f;
#pragma unroll
        for (int e = 0; e < 8; e++) { lg[e] = red[e][0]; m = fmaxf(m, lg[e]); }
        float pr[8];
#pragma unroll
        for (int e = 0; e < 8; e++) pr[e] = __expf(lg[e] - m);
        int i1 = 0;
#pragma unroll
        for (int e = 1; e < 8; e++) if (pr[e] > pr[i1]) i1 = e;
        int i2 = (i1 == 0) ? 1 : 0;
#pragma unroll
        for (int e = 0; e < 8; e++) if (e != i1 && pr[e] > pr[i2]) i2 = e;
        float v1 = pr[i1], v2 = pr[i2];
        float denom = v1 + v2;
        int pos1 = atomicAdd(&g_expcnt[i1], 1);
        g_toklist[i1 * LIST_STRIDE + pos1] = t * 2;
        g_entrygate[t * 2] = v1 / denom;
        int pos2 = atomicAdd(&g_expcnt[i2], 1);
        g_toklist[i2 * LIST_STRIDE + pos2] = t * 2 + 1;
        g_entrygate[t * 2 + 1] = v2 / denom;
    }
}

// ---------------- fp16 2-term HMMA GEMM: C[M,N] = (Ah+Al) @ B^T ----------------
// CTA tile 128x128, BK=32, 8 warps (2x4), warp tile 64x32, 3-stage, single sync.
// modes: 0 dense fp32 (+resid), 2 MoE-down atomic, 4 MoE gate/up interleaved + silu,
// 6 fused QKV epilogue (Q fp32 / K fp16 / V fp16 split).
#define STAGE_BYTES 24576
#define HM_SMEM (3 * STAGE_BYTES)

__device__ __forceinline__ uint32_t sw_addr(uint32_t base, int row, int kchunk) {
    return base + (uint32_t)(row * 64) + (uint32_t)((kchunk ^ ((row >> 1) & 3)) << 4);
}

__global__ __launch_bounds__(256) void hmma_gemm(
    const __half* __restrict__ Ahi, const __half* __restrict__ Alo,
    const __half* __restrict__ B,
    float* __restrict__ C, int N, int K,
    const float* __restrict__ resid, int mode) {
    extern __shared__ char dsm[];
    __shared__ int arowS[128];
    __shared__ int crowS[128];

    int tid = threadIdx.x;
    int n0 = blockIdx.x * 128;
    int mb = blockIdx.y * 128;
    int e = blockIdx.z;
    int cnt = 1 << 30;
    bool moe = (mode == 2 || mode == 4);
    if (moe) {
        cnt = g_expcnt[e];
        if (mb >= cnt) return;
        B += (size_t)e * N * K;
    }
    if (tid < 128) {
        if (moe) {
            int idx = mb + tid;
            if (idx > cnt - 1) idx = cnt - 1;
            int entry = g_toklist[e * LIST_STRIDE + idx];
            crowS[tid] = entry;
            arowS[tid] = (mode == 4) ? (entry >> 1) : entry;
        } else {
            arowS[tid] = mb + tid;
            crowS[tid] = mb + tid;
        }
    }
    __syncthreads();

    uint32_t sb = smem_u32(dsm);

    auto load_tile = [&](int stage, int k0) {
        uint32_t sbase = sb + (uint32_t)stage * STAGE_BYTES;
#pragma unroll
        for (int i = 0; i < 6; i++) {
            int ci = i * 256 + tid;  // 0..1535
            int mat = ci >> 9;       // 0=Ah 1=Al 2=B
            int idx = ci & 511;
            int r = idx >> 2, c = idx & 3;
            uint32_t dst = sw_addr(sbase + (uint32_t)mat * 8192u, r, c);
            const __half* src;
            if (mat == 0) src = Ahi + (size_t)arowS[r] * K + k0 + c * 8;
            else if (mat == 1) src = Alo + (size_t)arowS[r] * K + k0 + c * 8;
            else src = B + (size_t)(n0 + r) * K + k0 + c * 8;
            cpa16(dst, src);
        }
        cp_commit();
    };

    int T = K >> 5;
    load_tile(0, 0);
    load_tile(1, 32);

    int warp = tid >> 5, lane = tid & 31;
    int wm = warp >> 2, wn = warp & 3;
    int q = lane >> 3, sub = lane & 7;

    float acc[4][4][4];
#pragma unroll
    for (int mi = 0; mi < 4; mi++)
#pragma unroll
        for (int nj = 0; nj < 4; nj++)
#pragma unroll
            for (int v = 0; v < 4; v++) acc[mi][nj][v] = 0.f;

    for (int kt = 0; kt < T; kt++) {
        if (kt < T - 1) cp_wait1(); else cp_wait0();
        __syncthreads();
        if (kt + 2 < T) load_tile((kt + 2) % 3, (kt + 2) * 32);
        uint32_t sbase = sb + (uint32_t)(kt % 3) * STAGE_BYTES;
        uint32_t aH = sbase, aL = sbase + 8192u, bB = sbase + 16384u;
#pragma unroll
        for (int ks = 0; ks < 2; ks++) {
            uint32_t ah[4][4], al[4][4], bb[2][4];
#pragma unroll
            for (int mi = 0; mi < 4; mi++) {
                int row = wm * 64 + mi * 16 + (q & 1) * 8 + sub;
                int kc = ks * 2 + (q >> 1);
                ldsm_x4(ah[mi], sw_addr(aH, row, kc));
                ldsm_x4(al[mi], sw_addr(aL, row, kc));
            }
#pragma unroll
            for (int gj = 0; gj < 2; gj++) {
                int row = wn * 32 + gj * 16 + (q >> 1) * 8 + sub;
                int kc = ks * 2 + (q & 1);
                ldsm_x4(bb[gj], sw_addr(bB, row, kc));
            }
#pragma unroll
            for (int mi = 0; mi < 4; mi++)
#pragma unroll
                for (int nj = 0; nj < 4; nj++) {
                    const uint32_t* pb = &bb[nj >> 1][(nj & 1) * 2];
                    mma_16816h(acc[mi][nj], ah[mi], pb);
                    mma_16816h(acc[mi][nj], al[mi], pb);
                }
        }
    }

    int qr = lane >> 2, qc = lane & 3;
#pragma unroll
    for (int mi = 0; mi < 4; mi++) {
#pragma unroll
        for (int half = 0; half < 2; half++) {
            int rl = wm * 64 + mi * 16 + half * 8 + qr;
            if (moe && mb + rl >= cnt) continue;
            if (mode == 6) {
                int grow = mb + rl;
#pragma unroll
                for (int nj = 0; nj < 4; nj++) {
                    float v0 = acc[mi][nj][half * 2 + 0];
                    float v1 = acc[mi][nj][half * 2 + 1];
                    int col = n0 + wn * 32 + qc * 2 + nj * 8;
                    if (n0 < 2048) {
                        *(float2*)&C[(size_t)grow * 2048 + col] = make_float2(v0, v1);
                    } else if (n0 < 2560) {
                        *(float2*)&g_k[(size_t)grow * 512 + col - 2048] = make_float2(v0, v1);
                    } else {
                        size_t a = (size_t)grow * 512 + col - 2560;
                        __half2 hv = __floats2half2_rn(v0, v1);
                        *(__half2*)&g_v_hi[a] = hv;
                        *(__half2*)&g_v_lo[a] =
                            __floats2half2_rn(v0 - __half2float(hv.x),
                                              v1 - __half2float(hv.y));
                    }
                }
            } else if (mode == 4) {
                int entry = crowS[rl];
                float eg = g_entrygate[entry];
#pragma unroll
                for (int nj = 0; nj < 4; nj++) {
                    float gv = acc[mi][nj][half * 2 + 0];
                    float uv = acc[mi][nj][half * 2 + 1];
                    int f = (n0 + wn * 32 + qc * 2 + nj * 8) >> 1;
                    float a = eg * (gv / (1.f + __expf(-gv))) * uv;
                    size_t ai = (size_t)entry * NF + f;
                    split_store_h(a, g_act_hi + ai, g_act_lo + ai);
                }
            } else if (mode == 2) {
                size_t gbase = (size_t)(crowS[rl] >> 1) * N + n0 + wn * 32 + qc * 2;
#pragma unroll
                for (int nj = 0; nj < 4; nj++) {
                    atomicAdd(&C[gbase + nj * 8 + 0], acc[mi][nj][half * 2 + 0]);
                    atomicAdd(&C[gbase + nj * 8 + 1], acc[mi][nj][half * 2 + 1]);
                }
            } else {  // mode 0
                size_t gbase = (size_t)(mb + rl) * N + n0 + wn * 32 + qc * 2;
#pragma unroll
                for (int nj = 0; nj < 4; nj++) {
                    float v0 = acc[mi][nj][half * 2 + 0];
                    float v1 = acc[mi][nj][half * 2 + 1];
                    size_t addr = gbase + nj * 8;
                    if (resid) {
                        v0 += resid[addr + 0];
                        v1 += resid[addr + 1];
                    }
                    *(float2*)&C[addr] = make_float2(v0, v1);
                }
            }
        }
    }
}

// ---------------- host launch ----------------
extern "C" void kernel_launch(void* const* d_in, const int* in_sizes, int n_in,
                              void* d_out, int out_size) {
    const float* x          = (const float*)d_in[0];
    const float* wattn_norm = (const float*)d_in[1];
    const float* wq         = (const float*)d_in[2];
    const float* wk         = (const float*)d_in[3];
    const float* wv         = (const float*)d_in[4];
    const float* wq_norm    = (const float*)d_in[5];
    const float* wk_norm    = (const float*)d_in[6];
    const float* wattn_out  = (const float*)d_in[7];
    const float* wffn_norm  = (const float*)d_in[8];
    const float* w_router   = (const float*)d_in[9];
    const float* w_gate     = (const float*)d_in[10];
    const float* w_up       = (const float*)d_in[11];
    const float* w_down     = (const float*)d_in[12];
    float* out = (float*)d_out;

    cudaFuncSetAttribute(hmma_gemm, cudaFuncAttributeMaxDynamicSharedMemorySize, HM_SMEM);
    cudaFuncSetAttribute(attn_hmma, cudaFuncAttributeMaxDynamicSharedMemorySize, AT_SMEM);

    float *p_q, *p_k, *p_h2;
    cudaGetSymbolAddress((void**)&p_q, g_q);
    cudaGetSymbolAddress((void**)&p_k, g_k);
    cudaGetSymbolAddress((void**)&p_h2, g_h2);

    __half *hh, *hl, *h2h, *h2l, *oh, *ol, *ah, *al;
    __half *k16_, *vh_, *vl_;
    __half *wqkv_, *wo_, *wgu_, *wd_;
    cudaGetSymbolAddress((void**)&hh, g_h_hi);   cudaGetSymbolAddress((void**)&hl, g_h_lo);
    cudaGetSymbolAddress((void**)&h2h, g_h2_hi); cudaGetSymbolAddress((void**)&h2l, g_h2_lo);
    cudaGetSymbolAddress((void**)&oh, g_o_hi);   cudaGetSymbolAddress((void**)&ol, g_o_lo);
    cudaGetSymbolAddress((void**)&ah, g_act_hi); cudaGetSymbolAddress((void**)&al, g_act_lo);
    cudaGetSymbolAddress((void**)&k16_, g_k16);
    cudaGetSymbolAddress((void**)&vh_, g_v_hi);  cudaGetSymbolAddress((void**)&vl_, g_v_lo);
    cudaGetSymbolAddress((void**)&wqkv_, g_wqkv);
    cudaGetSymbolAddress((void**)&wo_, g_wo);
    cudaGetSymbolAddress((void**)&wgu_, g_wgu);
    cudaGetSymbolAddress((void**)&wd_, g_wd);

    // weight conversions (fp32 -> fp16 single)
    conv_kernel<<<512, 256>>>((const float4*)wq, (__half2*)wqkv_, 2048 * 512);
    conv_kernel<<<128, 256>>>((const float4*)wk, (__half2*)(wqkv_ + 2048 * 2048), 512 * 512);
    conv_kernel<<<128, 256>>>((const float4*)wv, (__half2*)(wqkv_ + 2560 * 2048), 512 * 512);
    // h = rmsnorm(x) -> fp16 split
    rmsnorm_split<<<T_TOK, 256>>>(x, wattn_norm, nullptr, hh, hl, 0);
    conv_kernel<<<512, 256>>>((const float4*)wattn_out, (__half2*)wo_, 2048 * 512);
    // fused QKV projection (fp16 2-term)
    hmma_gemm<<<dim3(24, 32, 1), 256, HM_SMEM>>>(hh, hl, wqkv_, p_q, 3072, 2048, nullptr, 6);
    // qk norm + rope (Q fp32 in-place; K -> single fp16)
    qknorm_rope<<<T_TOK * NH / 8, 256>>>(p_q, wq_norm, NH, nullptr);
    qknorm_rope<<<T_TOK * NKV / 8, 256>>>(p_k, wk_norm, NKV, k16_);
    // fp16 2-term flash attention -> O fp16 split
    attn_hmma<<<dim3(16, NH, 2), 256, AT_SMEM>>>(p_q, k16_, vh_, vl_, oh, ol);
    // out projection + residual -> d_out
    hmma_gemm<<<dim3(16, 32, 1), 256, HM_SMEM>>>(oh, ol, wo_, out, 2048, 2048, x, 0);
    // h2 = rmsnorm(out) (+ zero expert counters)
    rmsnorm_split<<<T_TOK, 256>>>(out, wffn_norm, p_h2, h2h, h2l, 1);
    // router
    router_kernel<<<T_TOK, 256>>>(p_h2, w_router);
    // MoE weight conversions
    conv_interleave<<<1024, 256>>>((const float4*)w_gate, (__half2*)wgu_, 0);
    conv_interleave<<<1024, 256>>>((const float4*)w_up, (__half2*)wgu_, 1);
    conv_kernel<<<1024, 256>>>((const float4*)w_down, (__half2*)wd_, NE * D_MODEL * 256);
    // fused gate/up GEMM + silu + router gate -> act fp16 split
    hmma_gemm<<<dim3(16, 64, NE), 256, HM_SMEM>>>(h2h, h2l, wgu_, nullptr, 2048, 2048, nullptr, 4);
    // down projection, scatter-add into out
    hmma_gemm<<<dim3(16, 64, NE), 256, HM_SMEM>>>(ah, al, wd_, out, D_MODEL, NF, nullptr, 2);
}